// round 4
// baseline (speedup 1.0000x reference)
#include <cuda_runtime.h>
#include <math.h>

#define TT    16384
#define AA    128
#define KK    128
#define NROW  4
#define NSTEP 16
#define EE    126
#define XSTR  260      // padded xc4 row stride in floats (multiple of 4)

// ---------------- device scratch (static: no allocations allowed) ----------
__device__ __align__(16) float              g_du[AA * KK];
__device__ __align__(16) float              g_xc4[AA * 4 * AA * XSTR]; // ~68MB
__device__ __align__(16) float              g_fm[NROW * AA * TT];
__device__ __align__(16) float              g_res[NROW * TT];
__device__ __align__(16) unsigned long long g_cm64[NROW * TT]; // (fenc(v)<<32)|(127-a)
__device__ __align__(16) float              g_emb[NROW * NSTEP * 128];
__device__ float                            g_norm[NROW];
__device__ int                              g_done;

// order-preserving float->uint encoding (monotone bijection)
__device__ __forceinline__ unsigned fenc(float f) {
    unsigned u = __float_as_uint(f);
    return (u & 0x80000000u) ? ~u : (u | 0x80000000u);
}
__device__ __forceinline__ float fdec(unsigned e) {
    return (e & 0x80000000u) ? __uint_as_float(e ^ 0x80000000u)
                             : __uint_as_float(~e);
}

// ---------------- prep: d_unit + residual/cm64 init + xc4 edge zero --------
__global__ void prep_kernel(const float* __restrict__ a,
                            const float* __restrict__ b,
                            const float* __restrict__ d)
{
    __shared__ float sred[4];
    int bx = blockIdx.x;
    int tid = threadIdx.x; // 128
    if (bx == 0 && tid == 0) g_done = 0;
    if (bx < AA) {
        float v = d[bx * KK + tid];
        float ss = v * v;
        #pragma unroll
        for (int off = 16; off; off >>= 1)
            ss += __shfl_down_sync(0xffffffffu, ss, off);
        if ((tid & 31) == 0) sred[tid >> 5] = ss;
        __syncthreads();
        float tot = sred[0] + sred[1] + sred[2] + sred[3];
        g_du[bx * KK + tid] = v / (sqrtf(tot) + 1e-8f);
    } else if (bx < 384) {
        int base = (bx - AA) * 256;
        #pragma unroll
        for (int j = tid; j < 256; j += 128) {
            int i = base + j;
            g_res[i] = (i < 2 * TT) ? a[i] : b[i - 2 * TT];
            g_cm64[i] = 0ull;
        }
    } else {
        // zero uncovered edges of g_xc4: for shift s, cols [0,s) and [256+s,260)
        int bb = bx - 384;           // 0..511
        int ai = bb >> 2, s = bb & 3;
        int aa2 = tid;
        #pragma unroll
        for (int idx = 0; idx < 4; idx++) {
            int jp = (idx < s) ? idx : 256 + idx;
            g_xc4[((ai * 4 + s) * AA + aa2) * XSTR + jp] = 0.f;
        }
    }
}

// ---------------- merged correlation kernel (fm + xcorr), f32x2 ------------
// blk <  1024 : fm    (row 0..3, tile 0..127, half 0..1) -> g_fm + colmax64
// blk >= 1024 : xcorr (row 0..127, tile 0..1, half 0..1) -> g_xc4 (4 shifts)
__global__ __launch_bounds__(256) void corr_kernel()
{
    __shared__ float s_du[KK][64];   // [k][a_local] 32KB
    __shared__ float s_sig[256];
    __shared__ float s_red[8][128];  // colmax value epilogue
    __shared__ unsigned char s_reda[8][128]; // colmax atom epilogue

    int blk = blockIdx.x;
    int tid = threadIdx.x; // 256

    int mode, row, tile, half;
    if (blk < 1024) { mode = 0; half = blk & 1; row = (blk >> 1) & 3; tile = blk >> 3; }
    else { int b2 = blk - 1024; mode = 1; half = b2 & 1; tile = (b2 >> 1) & 1; row = b2 >> 2; }
    int t0 = tile * 128;

    for (int i = tid; i < 64 * KK; i += 256) {
        int al = i >> 7, k = i & 127;
        s_du[k][al] = g_du[(half * 64 + al) * KK + k];
    }

    const float* src;
    int srcLen, shift;
    if (mode == 0) { src = g_res + row * TT; srcLen = TT; shift = 64; }
    else           { src = g_du + row * KK;  srcLen = KK; shift = 127; }

    {
        int t = t0 + tid - shift;
        s_sig[tid] = (t >= 0 && t < srcLen) ? src[t] : 0.f;
    }
    __syncthreads();

    int x = tid & 31, y = tid >> 5;
    int c0 = x * 4, a0 = y * 8;

    unsigned long long acc2[4][4];
    #pragma unroll
    for (int j = 0; j < 4; j++)
        #pragma unroll
        for (int c = 0; c < 4; c++) acc2[j][c] = 0ull;

    // loop-carried packed broadcast regs
    unsigned long long rr0, rr1, rr2, rr3;
    {
        unsigned u0 = __float_as_uint(s_sig[c0]);
        unsigned u1 = __float_as_uint(s_sig[c0 + 1]);
        unsigned u2 = __float_as_uint(s_sig[c0 + 2]);
        unsigned u3 = __float_as_uint(s_sig[c0 + 3]);
        asm("mov.b64 %0, {%1, %1};" : "=l"(rr0) : "r"(u0));
        asm("mov.b64 %0, {%1, %1};" : "=l"(rr1) : "r"(u1));
        asm("mov.b64 %0, {%1, %1};" : "=l"(rr2) : "r"(u2));
        asm("mov.b64 %0, {%1, %1};" : "=l"(rr3) : "r"(u3));
    }

    #pragma unroll 4
    for (int k = 0; k < KK; k++) {
        ulonglong2 p0 = *(const ulonglong2*)&s_du[k][a0];
        ulonglong2 p1 = *(const ulonglong2*)&s_du[k][a0 + 4];
        unsigned long long dv[4] = { p0.x, p0.y, p1.x, p1.y };

        #pragma unroll
        for (int j = 0; j < 4; j++) {
            asm("fma.rn.f32x2 %0, %1, %2, %0;" : "+l"(acc2[j][0]) : "l"(dv[j]), "l"(rr0));
            asm("fma.rn.f32x2 %0, %1, %2, %0;" : "+l"(acc2[j][1]) : "l"(dv[j]), "l"(rr1));
            asm("fma.rn.f32x2 %0, %1, %2, %0;" : "+l"(acc2[j][2]) : "l"(dv[j]), "l"(rr2));
            asm("fma.rn.f32x2 %0, %1, %2, %0;" : "+l"(acc2[j][3]) : "l"(dv[j]), "l"(rr3));
        }
        rr0 = rr1; rr1 = rr2; rr2 = rr3;
        unsigned rn = __float_as_uint(s_sig[c0 + 4 + k]);  // max idx 255, in bounds
        asm("mov.b64 %0, {%1, %1};" : "=l"(rr3) : "r"(rn));
    }

    int a_base = half * 64 + a0;
    int t = t0 + c0;

    if (mode == 0) {
        float* out = g_fm + row * AA * TT;
        float cmax[4] = { -3.402823466e38f, -3.402823466e38f,
                          -3.402823466e38f, -3.402823466e38f };
        int carg[4] = { 0, 0, 0, 0 };
        #pragma unroll
        for (int j = 0; j < 4; j++) {
            float lo[4], hi[4];
            #pragma unroll
            for (int c = 0; c < 4; c++) {
                lo[c] = __uint_as_float((unsigned)acc2[j][c]);
                hi[c] = __uint_as_float((unsigned)(acc2[j][c] >> 32));
                if (lo[c] > cmax[c]) { cmax[c] = lo[c]; carg[c] = a_base + 2 * j; }
                if (hi[c] > cmax[c]) { cmax[c] = hi[c]; carg[c] = a_base + 2 * j + 1; }
            }
            *(float4*)(out + (a_base + 2 * j) * TT + t) =
                make_float4(lo[0], lo[1], lo[2], lo[3]);
            *(float4*)(out + (a_base + 2 * j + 1) * TT + t) =
                make_float4(hi[0], hi[1], hi[2], hi[3]);
        }
        #pragma unroll
        for (int c = 0; c < 4; c++) {
            s_red[y][c0 + c] = cmax[c];
            s_reda[y][c0 + c] = (unsigned char)carg[c];
        }
        __syncthreads();
        if (tid < 128) {
            float m = s_red[0][tid];
            int am = s_reda[0][tid];
            #pragma unroll
            for (int w = 1; w < 8; w++) {
                float mw = s_red[w][tid];
                if (mw > m) { m = mw; am = s_reda[w][tid]; }  // ascending atoms
            }
            unsigned long long key =
                ((unsigned long long)fenc(m) << 32) | (unsigned)(127 - am);
            atomicMax(&g_cm64[row * TT + t0 + tid], key);
        }
    } else {
        // write 4 shifted copies: g_xc4[row][s][a][j + s] = xcorr[row][a][j]
        #pragma unroll
        for (int j = 0; j < 4; j++) {
            #pragma unroll
            for (int c = 0; c < 4; c++) {
                float lov = __uint_as_float((unsigned)acc2[j][c]);
                float hiv = __uint_as_float((unsigned)(acc2[j][c] >> 32));
                int jj = t + c;
                #pragma unroll
                for (int s = 0; s < 4; s++) {
                    long base = ((long)(row * 4 + s) * AA + a_base + 2 * j) * XSTR + jj + s;
                    g_xc4[base] = lov;
                    g_xc4[base + XSTR] = hiv;
                }
            }
        }
    }
}

// ---------------- all 16 matched-pursuit steps + fused final ---------------
// dynamic smem: s_cm (TT u32, 64KB) + s_ca (TT u8, 16KB) + s_tile (133KB)
__global__ __launch_bounds__(1024) void steps_kernel(const float* __restrict__ atom_emb,
                                                     const float* __restrict__ proj,
                                                     float* __restrict__ out)
{
    extern __shared__ unsigned char smem_raw[];
    unsigned*      s_cm   = (unsigned*)smem_raw;
    unsigned char* s_ca   = smem_raw + TT * 4;
    float*         s_tile = (float*)(smem_raw + TT * 4 + TT);

    __shared__ unsigned s_rk[32];
    __shared__ int      s_rt[32];
    __shared__ float    s_nred[32];
    __shared__ float sh_v;
    __shared__ int   sh_ti, sh_ai, sh_pa, sh_aa;
    __shared__ int   s_last;
    __shared__ float s_keys[64];
    __shared__ int   s_order[64];
    __shared__ float s_proj[128];

    int r = blockIdx.x;
    int tid = threadIdx.x;
    int lane = tid & 31, wid = tid >> 5;

    float* fmr  = g_fm  + r * AA * TT;
    float* resr = g_res + r * TT;

    // load initial colmax + argatom into smem
    #pragma unroll
    for (int q = 0; q < 16; q++) {
        int i = tid + 1024 * q;
        unsigned long long e = g_cm64[r * TT + i];
        s_cm[i] = (unsigned)(e >> 32);
        s_ca[i] = (unsigned char)(127 - ((unsigned)e & 0x7fu));
    }
    __syncthreads();

    for (int step = 0; step < NSTEP; step++) {
        // --- phase 1: global argmax over encoded s_cm (tie -> lowest t) ---
        unsigned bk = 0u;
        int bt = 0x7fffffff;
        #pragma unroll
        for (int q = 0; q < 4; q++) {
            uint4 u = ((const uint4*)s_cm)[tid + 1024 * q];
            int tb = (tid + 1024 * q) * 4;
            if (u.x > bk) { bk = u.x; bt = tb; }
            if (u.y > bk) { bk = u.y; bt = tb + 1; }
            if (u.z > bk) { bk = u.z; bt = tb + 2; }
            if (u.w > bk) { bk = u.w; bt = tb + 3; }
        }
        #pragma unroll
        for (int off = 16; off; off >>= 1) {
            unsigned ok = __shfl_down_sync(0xffffffffu, bk, off);
            int      ot = __shfl_down_sync(0xffffffffu, bt, off);
            if (ok > bk || (ok == bk && ot < bt)) { bk = ok; bt = ot; }
        }
        if (lane == 0) { s_rk[wid] = bk; s_rt[wid] = bt; }
        __syncthreads();

        // --- phase 2: warp 0 final reduce; atom from s_ca lookup ---
        if (wid == 0) {
            bk = s_rk[lane]; bt = s_rt[lane];
            #pragma unroll
            for (int off = 16; off; off >>= 1) {
                unsigned ok = __shfl_down_sync(0xffffffffu, bk, off);
                int      ot = __shfl_down_sync(0xffffffffu, bt, off);
                if (ok > bk || (ok == bk && ot < bt)) { bk = ok; bt = ot; }
            }
            if (lane == 0) {
                float av = fdec(bk);
                int aarg = s_ca[bt];
                sh_v = av; sh_ti = bt; sh_ai = aarg;
                int pa, aa2;
                if (av > 0.f)      { pa = bt; aa2 = aarg; }
                else if (av < 0.f) { pa = (bt == 0) ? 1 : 0; aa2 = (aarg == 0) ? 1 : 0; }
                else               { pa = 0; aa2 = 0; }
                sh_pa = pa; sh_aa = aa2;
            }
        }
        __syncthreads();

        float v = sh_v;
        int ti = sh_ti, ai = sh_ai;
        int w0  = (ti - 127) & ~3;        // aligned window start
        int shf = (ti - 127) - w0;        // 0..3

        // --- phase 3a: embedding + residual update ---
        if (tid < 128) {
            float e;
            if (tid == 0)      e = (float)sh_pa * (20.f / (float)(TT - 1));
            else if (tid == 1) e = v;
            else               e = atom_emb[sh_aa * EE + (tid - 2)];
            g_emb[(r * NSTEP + step) * 128 + tid] = e;
        } else if (tid < 256) {
            int k = tid - 128;
            int t = ti - 64 + k;
            if (t >= 0 && t < TT) resr[t] -= v * g_du[ai * KK + k];
        }

        // --- phase 3b: coalesced float4 window update (fm gmem + smem tile)
        {
            #pragma unroll
            for (int ii = 0; ii < 4; ii++) {
                int a = wid * 4 + ii;
                float*       fp = fmr + a * TT;
                const float* xp = g_xc4 + ((long)(ai * 4 + shf) * AA + a) * XSTR;
                float*       tp = s_tile + a * XSTR;
                #pragma unroll
                for (int it = 0; it < 3; it++) {
                    int jj4 = lane + 32 * it;
                    if (jj4 < 65) {
                        int jp = jj4 * 4;
                        int t = w0 + jp;
                        if (t >= 0 && t + 3 < TT) {
                            float4 f = *(const float4*)(fp + t);
                            float4 xx = *(const float4*)(xp + jp);
                            f.x -= v * xx.x; f.y -= v * xx.y;
                            f.z -= v * xx.z; f.w -= v * xx.w;
                            *(float4*)(fp + t) = f;
                            *(float4*)(tp + jp) = f;
                        } else {
                            #pragma unroll
                            for (int e = 0; e < 4; e++) {
                                int te = t + e;
                                if (te >= 0 && te < TT) {
                                    float f = fp[te] - v * xp[jp + e];
                                    fp[te] = f;
                                    tp[jp + e] = f;
                                }
                            }
                        }
                    }
                }
            }
        }
        __syncthreads();

        // --- phase 4: exact colmax+arg recompute from smem tile ------------
        // 65 col-quads x 16 atom-groups; 16-lane shfl reduce; single writer.
        {
            #pragma unroll
            for (int pass = 0; pass < 2; pass++) {
                int g, sub;
                unsigned msk;
                bool active;
                if (pass == 0) { g = tid >> 4; sub = tid & 15; msk = 0xffffffffu; active = true; }
                else { g = 64; sub = tid; msk = 0xffffu; active = (tid < 16); }
                if (!active) break;

                float m0 = -3.402823466e38f, m1 = m0, m2 = m0, m3 = m0;
                int a0i = 0, a1i = 0, a2i = 0, a3i = 0;
                #pragma unroll
                for (int i = 0; i < 8; i++) {
                    int a = sub * 8 + i;
                    float4 xx = *(const float4*)(s_tile + a * XSTR + 4 * g);
                    if (xx.x > m0) { m0 = xx.x; a0i = a; }
                    if (xx.y > m1) { m1 = xx.y; a1i = a; }
                    if (xx.z > m2) { m2 = xx.z; a2i = a; }
                    if (xx.w > m3) { m3 = xx.w; a3i = a; }
                }
                unsigned long long k0 = ((unsigned long long)fenc(m0) << 32) | (unsigned)(127 - a0i);
                unsigned long long k1 = ((unsigned long long)fenc(m1) << 32) | (unsigned)(127 - a1i);
                unsigned long long k2 = ((unsigned long long)fenc(m2) << 32) | (unsigned)(127 - a2i);
                unsigned long long k3 = ((unsigned long long)fenc(m3) << 32) | (unsigned)(127 - a3i);
                #pragma unroll
                for (int off = 1; off < 16; off <<= 1) {
                    unsigned long long o0 = __shfl_xor_sync(msk, k0, off);
                    unsigned long long o1 = __shfl_xor_sync(msk, k1, off);
                    unsigned long long o2 = __shfl_xor_sync(msk, k2, off);
                    unsigned long long o3 = __shfl_xor_sync(msk, k3, off);
                    if (o0 > k0) k0 = o0;
                    if (o1 > k1) k1 = o1;
                    if (o2 > k2) k2 = o2;
                    if (o3 > k3) k3 = o3;
                }
                if (sub == 0) {
                    int tb = w0 + 4 * g;
                    if (tb >= 0 && tb < TT) {
                        s_cm[tb] = (unsigned)(k0 >> 32);
                        s_ca[tb] = (unsigned char)(127 - ((unsigned)k0 & 0x7fu));
                    }
                    if (tb + 1 >= 0 && tb + 1 < TT) {
                        s_cm[tb + 1] = (unsigned)(k1 >> 32);
                        s_ca[tb + 1] = (unsigned char)(127 - ((unsigned)k1 & 0x7fu));
                    }
                    if (tb + 2 >= 0 && tb + 2 < TT) {
                        s_cm[tb + 2] = (unsigned)(k2 >> 32);
                        s_ca[tb + 2] = (unsigned char)(127 - ((unsigned)k2 & 0x7fu));
                    }
                    if (tb + 3 >= 0 && tb + 3 < TT) {
                        s_cm[tb + 3] = (unsigned)(k3 >> 32);
                        s_ca[tb + 3] = (unsigned char)(127 - ((unsigned)k3 & 0x7fu));
                    }
                }
            }
        }
        __syncthreads();
    }

    // --- residual norm (fused) ---
    float ss = 0.f;
    #pragma unroll
    for (int q = 0; q < 4; q++) {
        float4 vv = ((const float4*)resr)[tid + 1024 * q];
        ss += vv.x * vv.x + vv.y * vv.y + vv.z * vv.z + vv.w * vv.w;
    }
    #pragma unroll
    for (int off = 16; off; off >>= 1)
        ss += __shfl_down_sync(0xffffffffu, ss, off);
    if (lane == 0) s_nred[wid] = ss;
    __syncthreads();
    if (wid == 0) {
        float t2 = s_nred[lane];
        #pragma unroll
        for (int off = 16; off; off >>= 1)
            t2 += __shfl_down_sync(0xffffffffu, t2, off);
        if (lane == 0) g_norm[r] = sqrtf(t2);
    }

    // --- fused final loss: last block to finish computes it ---
    __threadfence();
    __syncthreads();
    if (tid == 0) s_last = (atomicAdd(&g_done, 1) == NROW - 1);
    __syncthreads();
    if (!s_last) return;
    __threadfence();

    if (tid < 128) s_proj[tid] = proj[tid];
    __syncthreads();

    // keys: 32 warps x 2 keys (16 lanes per key)
    {
        int key = wid * 2 + (lane >> 4);
        int sl = lane & 15;
        const float* e = g_emb + key * 128;
        float p = 0.f;
        #pragma unroll
        for (int q = 0; q < 8; q++) {
            int j = sl + 16 * q;
            p += e[j] * s_proj[j];
        }
        #pragma unroll
        for (int off = 1; off < 16; off <<= 1)
            p += __shfl_xor_sync(0xffffffffu, p, off);
        if (sl == 0) s_keys[key] = p;
    }
    __syncthreads();

    if (tid < 4) {   // stable insertion sort, ascending (matches jnp.argsort)
        int ord[16];
        for (int i = 0; i < 16; i++) ord[i] = i;
        for (int i = 1; i < 16; i++) {
            int oi = ord[i];
            float ki = s_keys[tid * 16 + oi];
            int j = i - 1;
            while (j >= 0 && s_keys[tid * 16 + ord[j]] > ki) { ord[j + 1] = ord[j]; j--; }
            ord[j + 1] = oi;
        }
        for (int i = 0; i < 16; i++) s_order[tid * 16 + i] = ord[i];
    }
    __syncthreads();

    float acc = 0.f;
    #pragma unroll
    for (int q = 0; q < 4; q++) {
        int i = tid + 1024 * q;
        int bb = i >> 11;
        int st = (i >> 7) & 15;
        int e = i & 127;
        int sa = s_order[bb * 16 + st];
        int sb = s_order[(2 + bb) * 16 + st];
        float dd = g_emb[(bb * 16 + sa) * 128 + e] - g_emb[((2 + bb) * 16 + sb) * 128 + e];
        acc += dd * dd;
    }
    #pragma unroll
    for (int off = 16; off; off >>= 1)
        acc += __shfl_down_sync(0xffffffffu, acc, off);
    if (lane == 0) s_nred[wid] = acc;
    __syncthreads();
    if (tid == 0) {
        float t2 = 0.f;
        for (int w = 0; w < 32; w++) t2 += s_nred[w];
        out[0] = t2 / 4096.f
               + 0.5f * (fabsf(g_norm[0] - g_norm[2]) + fabsf(g_norm[1] - g_norm[3]));
    }
}

// ---------------- launch ----------------------------------------------------
#define SMEM_STEPS (TT * 4 + TT + AA * XSTR * 4)  // 65536+16384+133120 = 215040

extern "C" void kernel_launch(void* const* d_in, const int* in_sizes, int n_in,
                              void* d_out, int out_size)
{
    (void)in_sizes; (void)n_in; (void)out_size;
    const float* a    = (const float*)d_in[0];
    const float* b    = (const float*)d_in[1];
    const float* d    = (const float*)d_in[2];
    const float* aemb = (const float*)d_in[3];
    const float* proj = (const float*)d_in[4];
    float* out = (float*)d_out;

    cudaFuncSetAttribute(steps_kernel,
                         cudaFuncAttributeMaxDynamicSharedMemorySize, SMEM_STEPS);

    prep_kernel<<<896, 128>>>(a, b, d);
    corr_kernel<<<1536, 256>>>();                 // fm (1024) + xcorr->xc4 (512)
    steps_kernel<<<4, 1024, SMEM_STEPS>>>(aemb, proj, out);
}

// round 5
// speedup vs baseline: 1.0926x; 1.0926x over previous
#include <cuda_runtime.h>
#include <math.h>

#define TT    16384
#define AA    128
#define KK    128
#define NROW  4
#define NSTEP 16
#define EE    126
#define XSTR  260      // padded xc4 row stride in floats (multiple of 4)

// ---------------- device scratch (static: no allocations allowed) ----------
__device__ __align__(16) float              g_du[AA * KK];
__device__ __align__(16) float              g_xc4[AA * 4 * AA * XSTR]; // ~68MB
__device__ __align__(16) float              g_fm[NROW * AA * TT];
__device__ __align__(16) float              g_res[NROW * TT];
__device__ __align__(16) unsigned long long g_cm64[NROW * TT]; // (fenc(v)<<32)|(127-a)
__device__ __align__(16) float              g_emb[NROW * NSTEP * 128];
__device__ float                            g_norm[NROW];
__device__ int                              g_done;

// order-preserving float->uint encoding (monotone bijection)
__device__ __forceinline__ unsigned fenc(float f) {
    unsigned u = __float_as_uint(f);
    return (u & 0x80000000u) ? ~u : (u | 0x80000000u);
}
__device__ __forceinline__ float fdec(unsigned e) {
    return (e & 0x80000000u) ? __uint_as_float(e ^ 0x80000000u)
                             : __uint_as_float(~e);
}

// ---------------- prep: d_unit + residual/cm64 init + xc4 edge zero --------
__global__ void prep_kernel(const float* __restrict__ a,
                            const float* __restrict__ b,
                            const float* __restrict__ d)
{
    __shared__ float sred[4];
    int bx = blockIdx.x;
    int tid = threadIdx.x; // 128
    if (bx == 0 && tid == 0) g_done = 0;
    if (bx < AA) {
        float v = d[bx * KK + tid];
        float ss = v * v;
        #pragma unroll
        for (int off = 16; off; off >>= 1)
            ss += __shfl_down_sync(0xffffffffu, ss, off);
        if ((tid & 31) == 0) sred[tid >> 5] = ss;
        __syncthreads();
        float tot = sred[0] + sred[1] + sred[2] + sred[3];
        g_du[bx * KK + tid] = v / (sqrtf(tot) + 1e-8f);
    } else if (bx < 384) {
        int base = (bx - AA) * 256;
        #pragma unroll
        for (int j = tid; j < 256; j += 128) {
            int i = base + j;
            g_res[i] = (i < 2 * TT) ? a[i] : b[i - 2 * TT];
            g_cm64[i] = 0ull;
        }
    } else {
        // zero uncovered edges of g_xc4: for shift s, cols [0,s) and [256+s,260)
        int bb = bx - 384;           // 0..511
        int ai = bb >> 2, s = bb & 3;
        int aa2 = tid;
        #pragma unroll
        for (int idx = 0; idx < 4; idx++) {
            int jp = (idx < s) ? idx : 256 + idx;
            g_xc4[((ai * 4 + s) * AA + aa2) * XSTR + jp] = 0.f;
        }
    }
}

// ---------------- merged correlation kernel (fm + xcorr), f32x2 ------------
// blk <  1024 : fm    (row 0..3, tile 0..127, half 0..1) -> g_fm + colmax64
// blk >= 1024 : xcorr (row 0..127, tile 0..1, half 0..1) -> g_xc4 (4 shifts)
__global__ __launch_bounds__(256) void corr_kernel()
{
    __shared__ float s_du[KK][64];   // [k][a_local] 32KB
    __shared__ float s_sig[256];
    __shared__ float s_red[8][128];  // colmax value epilogue
    __shared__ unsigned char s_reda[8][128]; // colmax atom epilogue

    int blk = blockIdx.x;
    int tid = threadIdx.x; // 256

    int mode, row, tile, half;
    if (blk < 1024) { mode = 0; half = blk & 1; row = (blk >> 1) & 3; tile = blk >> 3; }
    else { int b2 = blk - 1024; mode = 1; half = b2 & 1; tile = (b2 >> 1) & 1; row = b2 >> 2; }
    int t0 = tile * 128;

    for (int i = tid; i < 64 * KK; i += 256) {
        int al = i >> 7, k = i & 127;
        s_du[k][al] = g_du[(half * 64 + al) * KK + k];
    }

    const float* src;
    int srcLen, shift;
    if (mode == 0) { src = g_res + row * TT; srcLen = TT; shift = 64; }
    else           { src = g_du + row * KK;  srcLen = KK; shift = 127; }

    {
        int t = t0 + tid - shift;
        s_sig[tid] = (t >= 0 && t < srcLen) ? src[t] : 0.f;
    }
    __syncthreads();

    int x = tid & 31, y = tid >> 5;
    int c0 = x * 4, a0 = y * 8;

    unsigned long long acc2[4][4];
    #pragma unroll
    for (int j = 0; j < 4; j++)
        #pragma unroll
        for (int c = 0; c < 4; c++) acc2[j][c] = 0ull;

    // loop-carried packed broadcast regs
    unsigned long long rr0, rr1, rr2, rr3;
    {
        unsigned u0 = __float_as_uint(s_sig[c0]);
        unsigned u1 = __float_as_uint(s_sig[c0 + 1]);
        unsigned u2 = __float_as_uint(s_sig[c0 + 2]);
        unsigned u3 = __float_as_uint(s_sig[c0 + 3]);
        asm("mov.b64 %0, {%1, %1};" : "=l"(rr0) : "r"(u0));
        asm("mov.b64 %0, {%1, %1};" : "=l"(rr1) : "r"(u1));
        asm("mov.b64 %0, {%1, %1};" : "=l"(rr2) : "r"(u2));
        asm("mov.b64 %0, {%1, %1};" : "=l"(rr3) : "r"(u3));
    }

    #pragma unroll 4
    for (int k = 0; k < KK; k++) {
        ulonglong2 p0 = *(const ulonglong2*)&s_du[k][a0];
        ulonglong2 p1 = *(const ulonglong2*)&s_du[k][a0 + 4];
        unsigned long long dv[4] = { p0.x, p0.y, p1.x, p1.y };

        #pragma unroll
        for (int j = 0; j < 4; j++) {
            asm("fma.rn.f32x2 %0, %1, %2, %0;" : "+l"(acc2[j][0]) : "l"(dv[j]), "l"(rr0));
            asm("fma.rn.f32x2 %0, %1, %2, %0;" : "+l"(acc2[j][1]) : "l"(dv[j]), "l"(rr1));
            asm("fma.rn.f32x2 %0, %1, %2, %0;" : "+l"(acc2[j][2]) : "l"(dv[j]), "l"(rr2));
            asm("fma.rn.f32x2 %0, %1, %2, %0;" : "+l"(acc2[j][3]) : "l"(dv[j]), "l"(rr3));
        }
        rr0 = rr1; rr1 = rr2; rr2 = rr3;
        unsigned rn = __float_as_uint(s_sig[c0 + 4 + k]);  // max idx 255, in bounds
        asm("mov.b64 %0, {%1, %1};" : "=l"(rr3) : "r"(rn));
    }

    int a_base = half * 64 + a0;
    int t = t0 + c0;

    if (mode == 0) {
        float* out = g_fm + row * AA * TT;
        float cmax[4] = { -3.402823466e38f, -3.402823466e38f,
                          -3.402823466e38f, -3.402823466e38f };
        int carg[4] = { 0, 0, 0, 0 };
        #pragma unroll
        for (int j = 0; j < 4; j++) {
            float lo[4], hi[4];
            #pragma unroll
            for (int c = 0; c < 4; c++) {
                lo[c] = __uint_as_float((unsigned)acc2[j][c]);
                hi[c] = __uint_as_float((unsigned)(acc2[j][c] >> 32));
                if (lo[c] > cmax[c]) { cmax[c] = lo[c]; carg[c] = a_base + 2 * j; }
                if (hi[c] > cmax[c]) { cmax[c] = hi[c]; carg[c] = a_base + 2 * j + 1; }
            }
            *(float4*)(out + (a_base + 2 * j) * TT + t) =
                make_float4(lo[0], lo[1], lo[2], lo[3]);
            *(float4*)(out + (a_base + 2 * j + 1) * TT + t) =
                make_float4(hi[0], hi[1], hi[2], hi[3]);
        }
        #pragma unroll
        for (int c = 0; c < 4; c++) {
            s_red[y][c0 + c] = cmax[c];
            s_reda[y][c0 + c] = (unsigned char)carg[c];
        }
        __syncthreads();
        if (tid < 128) {
            float m = s_red[0][tid];
            int am = s_reda[0][tid];
            #pragma unroll
            for (int w = 1; w < 8; w++) {
                float mw = s_red[w][tid];
                if (mw > m) { m = mw; am = s_reda[w][tid]; }  // ascending atoms
            }
            unsigned long long key =
                ((unsigned long long)fenc(m) << 32) | (unsigned)(127 - am);
            atomicMax(&g_cm64[row * TT + t0 + tid], key);
        }
    } else {
        // write 4 shifted copies: g_xc4[row][s][a][j + s] = xcorr[row][a][j]
        #pragma unroll
        for (int j = 0; j < 4; j++) {
            #pragma unroll
            for (int c = 0; c < 4; c++) {
                float lov = __uint_as_float((unsigned)acc2[j][c]);
                float hiv = __uint_as_float((unsigned)(acc2[j][c] >> 32));
                int jj = t + c;
                #pragma unroll
                for (int s = 0; s < 4; s++) {
                    long base = ((long)(row * 4 + s) * AA + a_base + 2 * j) * XSTR + jj + s;
                    g_xc4[base] = lov;
                    g_xc4[base + XSTR] = hiv;
                }
            }
        }
    }
}

// ---------------- all 16 matched-pursuit steps + fused final ---------------
// dynamic smem: s_cm (TT u32, 64KB) + s_ca (TT u8, 16KB) + s_tile (133KB)
__global__ __launch_bounds__(1024) void steps_kernel(const float* __restrict__ atom_emb,
                                                     const float* __restrict__ proj,
                                                     float* __restrict__ out)
{
    extern __shared__ unsigned char smem_raw[];
    unsigned*      s_cm   = (unsigned*)smem_raw;
    unsigned char* s_ca   = smem_raw + TT * 4;
    float*         s_tile = (float*)(smem_raw + TT * 4 + TT);

    __shared__ unsigned long long s_w64[260];  // window colmax combine buffer
    __shared__ unsigned s_rk[32];
    __shared__ int      s_rt[32];
    __shared__ float    s_nred[32];
    __shared__ float sh_v;
    __shared__ int   sh_ti, sh_ai, sh_pa, sh_aa;
    __shared__ int   s_last;
    __shared__ float s_keys[64];
    __shared__ int   s_order[64];
    __shared__ float s_proj[128];

    int r = blockIdx.x;
    int tid = threadIdx.x;
    int lane = tid & 31, wid = tid >> 5;

    float* fmr  = g_fm  + r * AA * TT;
    float* resr = g_res + r * TT;

    // load initial colmax + argatom into smem
    #pragma unroll
    for (int q = 0; q < 16; q++) {
        int i = tid + 1024 * q;
        unsigned long long e = g_cm64[r * TT + i];
        s_cm[i] = (unsigned)(e >> 32);
        s_ca[i] = (unsigned char)(127 - ((unsigned)e & 0x7fu));
    }
    __syncthreads();

    for (int step = 0; step < NSTEP; step++) {
        // --- phase 1: global argmax over encoded s_cm (tie -> lowest t) ---
        unsigned bk = 0u;
        int bt = 0x7fffffff;
        #pragma unroll
        for (int q = 0; q < 4; q++) {
            uint4 u = ((const uint4*)s_cm)[tid + 1024 * q];
            int tb = (tid + 1024 * q) * 4;
            if (u.x > bk) { bk = u.x; bt = tb; }
            if (u.y > bk) { bk = u.y; bt = tb + 1; }
            if (u.z > bk) { bk = u.z; bt = tb + 2; }
            if (u.w > bk) { bk = u.w; bt = tb + 3; }
        }
        #pragma unroll
        for (int off = 16; off; off >>= 1) {
            unsigned ok = __shfl_down_sync(0xffffffffu, bk, off);
            int      ot = __shfl_down_sync(0xffffffffu, bt, off);
            if (ok > bk || (ok == bk && ot < bt)) { bk = ok; bt = ot; }
        }
        if (lane == 0) { s_rk[wid] = bk; s_rt[wid] = bt; }
        __syncthreads();

        // --- phase 2: warp 0 final reduce; atom from s_ca lookup ---
        if (wid == 0) {
            bk = s_rk[lane]; bt = s_rt[lane];
            #pragma unroll
            for (int off = 16; off; off >>= 1) {
                unsigned ok = __shfl_down_sync(0xffffffffu, bk, off);
                int      ot = __shfl_down_sync(0xffffffffu, bt, off);
                if (ok > bk || (ok == bk && ot < bt)) { bk = ok; bt = ot; }
            }
            if (lane == 0) {
                float av = fdec(bk);
                int aarg = s_ca[bt];
                sh_v = av; sh_ti = bt; sh_ai = aarg;
                int pa, aa2;
                if (av > 0.f)      { pa = bt; aa2 = aarg; }
                else if (av < 0.f) { pa = (bt == 0) ? 1 : 0; aa2 = (aarg == 0) ? 1 : 0; }
                else               { pa = 0; aa2 = 0; }
                sh_pa = pa; sh_aa = aa2;
            }
        }
        __syncthreads();

        float v = sh_v;
        int ti = sh_ti, ai = sh_ai;
        int w0  = (ti - 127) & ~3;        // aligned window start
        int shf = (ti - 127) - w0;        // 0..3

        // --- phase 3a: embedding + residual update + s_w64 reset ---
        if (tid < 128) {
            float e;
            if (tid == 0)      e = (float)sh_pa * (20.f / (float)(TT - 1));
            else if (tid == 1) e = v;
            else               e = atom_emb[sh_aa * EE + (tid - 2)];
            g_emb[(r * NSTEP + step) * 128 + tid] = e;
        } else if (tid < 256) {
            int k = tid - 128;
            int t = ti - 64 + k;
            if (t >= 0 && t < TT) resr[t] -= v * g_du[ai * KK + k];
        } else if (tid < 516) {
            s_w64[tid - 256] = 0ull;
        }

        // --- phase 3b: coalesced float4 window update (fm gmem + smem tile)
        {
            #pragma unroll
            for (int ii = 0; ii < 4; ii++) {
                int a = wid * 4 + ii;
                float*       fp = fmr + a * TT;
                const float* xp = g_xc4 + ((long)(ai * 4 + shf) * AA + a) * XSTR;
                float*       tp = s_tile + a * XSTR;
                #pragma unroll
                for (int it = 0; it < 3; it++) {
                    int jj4 = lane + 32 * it;
                    if (jj4 < 65) {
                        int jp = jj4 * 4;
                        int t = w0 + jp;
                        if (t >= 0 && t + 3 < TT) {
                            float4 f = *(const float4*)(fp + t);
                            float4 xx = *(const float4*)(xp + jp);
                            f.x -= v * xx.x; f.y -= v * xx.y;
                            f.z -= v * xx.z; f.w -= v * xx.w;
                            *(float4*)(fp + t) = f;
                            *(float4*)(tp + jp) = f;
                        } else {
                            #pragma unroll
                            for (int e = 0; e < 4; e++) {
                                int te = t + e;
                                if (te >= 0 && te < TT) {
                                    float f = fp[te] - v * xp[jp + e];
                                    fp[te] = f;
                                    tp[jp + e] = f;
                                }
                            }
                        }
                    }
                }
            }
        }
        __syncthreads();

        // --- phase 4: colmax+arg partials (conflict-free col-across-lanes
        //     mapping) combined exactly via u64 smem atomicMax -------------
        {
            int c4 = tid & 63, sub = tid >> 6;    // 16 subs x 8 atoms
            #pragma unroll
            for (int pass = 0; pass < 2; pass++) {
                int cc4, ss;
                if (pass == 0) { cc4 = c4; ss = sub; }
                else { if (tid >= 16) break; cc4 = 64; ss = tid; }

                float m0 = -3.402823466e38f, m1 = m0, m2 = m0, m3 = m0;
                int a0i = 0, a1i = 0, a2i = 0, a3i = 0;
                #pragma unroll
                for (int i = 0; i < 8; i++) {
                    int a = ss * 8 + i;
                    float4 xx = *(const float4*)(s_tile + a * XSTR + 4 * cc4);
                    if (xx.x > m0) { m0 = xx.x; a0i = a; }
                    if (xx.y > m1) { m1 = xx.y; a1i = a; }
                    if (xx.z > m2) { m2 = xx.z; a2i = a; }
                    if (xx.w > m3) { m3 = xx.w; a3i = a; }
                }
                int cb = 4 * cc4;
                atomicMax(&s_w64[cb],
                          ((unsigned long long)fenc(m0) << 32) | (unsigned)(127 - a0i));
                atomicMax(&s_w64[cb + 1],
                          ((unsigned long long)fenc(m1) << 32) | (unsigned)(127 - a1i));
                atomicMax(&s_w64[cb + 2],
                          ((unsigned long long)fenc(m2) << 32) | (unsigned)(127 - a2i));
                atomicMax(&s_w64[cb + 3],
                          ((unsigned long long)fenc(m3) << 32) | (unsigned)(127 - a3i));
            }
        }
        __syncthreads();

        // --- phase 5: convert window keys into s_cm / s_ca ---
        if (tid < 260) {
            int t = w0 + tid;
            if (t >= 0 && t < TT) {
                unsigned long long k = s_w64[tid];
                s_cm[t] = (unsigned)(k >> 32);
                s_ca[t] = (unsigned char)(127 - ((unsigned)k & 0x7fu));
            }
        }
        __syncthreads();
    }

    // --- residual norm (fused) ---
    float ss = 0.f;
    #pragma unroll
    for (int q = 0; q < 4; q++) {
        float4 vv = ((const float4*)resr)[tid + 1024 * q];
        ss += vv.x * vv.x + vv.y * vv.y + vv.z * vv.z + vv.w * vv.w;
    }
    #pragma unroll
    for (int off = 16; off; off >>= 1)
        ss += __shfl_down_sync(0xffffffffu, ss, off);
    if (lane == 0) s_nred[wid] = ss;
    __syncthreads();
    if (wid == 0) {
        float t2 = s_nred[lane];
        #pragma unroll
        for (int off = 16; off; off >>= 1)
            t2 += __shfl_down_sync(0xffffffffu, t2, off);
        if (lane == 0) g_norm[r] = sqrtf(t2);
    }

    // --- fused final loss: last block to finish computes it ---
    __threadfence();
    __syncthreads();
    if (tid == 0) s_last = (atomicAdd(&g_done, 1) == NROW - 1);
    __syncthreads();
    if (!s_last) return;
    __threadfence();

    if (tid < 128) s_proj[tid] = proj[tid];
    __syncthreads();

    // keys: 32 warps x 2 keys (16 lanes per key)
    {
        int key = wid * 2 + (lane >> 4);
        int sl = lane & 15;
        const float* e = g_emb + key * 128;
        float p = 0.f;
        #pragma unroll
        for (int q = 0; q < 8; q++) {
            int j = sl + 16 * q;
            p += e[j] * s_proj[j];
        }
        #pragma unroll
        for (int off = 1; off < 16; off <<= 1)
            p += __shfl_xor_sync(0xffffffffu, p, off);
        if (sl == 0) s_keys[key] = p;
    }
    __syncthreads();

    if (tid < 4) {   // stable insertion sort, ascending (matches jnp.argsort)
        int ord[16];
        for (int i = 0; i < 16; i++) ord[i] = i;
        for (int i = 1; i < 16; i++) {
            int oi = ord[i];
            float ki = s_keys[tid * 16 + oi];
            int j = i - 1;
            while (j >= 0 && s_keys[tid * 16 + ord[j]] > ki) { ord[j + 1] = ord[j]; j--; }
            ord[j + 1] = oi;
        }
        for (int i = 0; i < 16; i++) s_order[tid * 16 + i] = ord[i];
    }
    __syncthreads();

    float acc = 0.f;
    #pragma unroll
    for (int q = 0; q < 4; q++) {
        int i = tid + 1024 * q;
        int bb = i >> 11;
        int st = (i >> 7) & 15;
        int e = i & 127;
        int sa = s_order[bb * 16 + st];
        int sb = s_order[(2 + bb) * 16 + st];
        float dd = g_emb[(bb * 16 + sa) * 128 + e] - g_emb[((2 + bb) * 16 + sb) * 128 + e];
        acc += dd * dd;
    }
    #pragma unroll
    for (int off = 16; off; off >>= 1)
        acc += __shfl_down_sync(0xffffffffu, acc, off);
    if (lane == 0) s_nred[wid] = acc;
    __syncthreads();
    if (tid == 0) {
        float t2 = 0.f;
        for (int w = 0; w < 32; w++) t2 += s_nred[w];
        out[0] = t2 / 4096.f
               + 0.5f * (fabsf(g_norm[0] - g_norm[2]) + fabsf(g_norm[1] - g_norm[3]));
    }
}

// ---------------- launch ----------------------------------------------------
#define SMEM_STEPS (TT * 4 + TT + AA * XSTR * 4)  // 65536+16384+133120 = 215040

extern "C" void kernel_launch(void* const* d_in, const int* in_sizes, int n_in,
                              void* d_out, int out_size)
{
    (void)in_sizes; (void)n_in; (void)out_size;
    const float* a    = (const float*)d_in[0];
    const float* b    = (const float*)d_in[1];
    const float* d    = (const float*)d_in[2];
    const float* aemb = (const float*)d_in[3];
    const float* proj = (const float*)d_in[4];
    float* out = (float*)d_out;

    cudaFuncSetAttribute(steps_kernel,
                         cudaFuncAttributeMaxDynamicSharedMemorySize, SMEM_STEPS);

    prep_kernel<<<896, 128>>>(a, b, d);
    corr_kernel<<<1536, 256>>>();                 // fm (1024) + xcorr->xc4 (512)
    steps_kernel<<<4, 1024, SMEM_STEPS>>>(aemb, proj, out);
}

// round 8
// speedup vs baseline: 1.1742x; 1.0746x over previous
#include <cuda_runtime.h>
#include <math.h>

#define TT    16384
#define AA    128
#define KK    128
#define NROW  4
#define NSTEP 16
#define EE    126
#define XSTR  260      // padded xc4 row stride in floats; 65 float4 ≡ 1 mod 8 (conflict-free)

// ---------------- device scratch (static: no allocations allowed) ----------
__device__ __align__(16) float    g_du[AA * KK];
__device__ __align__(16) float    g_xc4[AA * 4 * AA * XSTR]; // ~68MB
__device__ __align__(16) float    g_fm[NROW * AA * TT];
__device__ __align__(16) float    g_res[NROW * TT];
__device__ __align__(16) unsigned g_cm[NROW * TT];           // encoded colmax
__device__ __align__(16) float    g_emb[NROW * NSTEP * 128];
__device__ float                  g_norm[NROW];
__device__ int                    g_done;

// order-preserving float->uint encoding (monotone bijection)
__device__ __forceinline__ unsigned fenc(float f) {
    unsigned u = __float_as_uint(f);
    return (u & 0x80000000u) ? ~u : (u | 0x80000000u);
}

// ---------------- prep: d_unit + residual/cm init + xc4 edge zero ----------
__global__ void prep_kernel(const float* __restrict__ a,
                            const float* __restrict__ b,
                            const float* __restrict__ d)
{
    __shared__ float sred[4];
    int bx = blockIdx.x;
    int tid = threadIdx.x; // 128
    if (bx == 0 && tid == 0) g_done = 0;
    if (bx < AA) {
        float v = d[bx * KK + tid];
        float ss = v * v;
        #pragma unroll
        for (int off = 16; off; off >>= 1)
            ss += __shfl_down_sync(0xffffffffu, ss, off);
        if ((tid & 31) == 0) sred[tid >> 5] = ss;
        __syncthreads();
        float tot = sred[0] + sred[1] + sred[2] + sred[3];
        g_du[bx * KK + tid] = v / (sqrtf(tot) + 1e-8f);
    } else if (bx < 384) {
        int base = (bx - AA) * 256;
        #pragma unroll
        for (int j = tid; j < 256; j += 128) {
            int i = base + j;
            g_res[i] = (i < 2 * TT) ? a[i] : b[i - 2 * TT];
            g_cm[i] = 0u;
        }
    } else {
        // zero uncovered edges of g_xc4: for shift s, cols [0,s) and [256+s,260)
        int bb = bx - 384;           // 0..511
        int ai = bb >> 2, s = bb & 3;
        int aa2 = tid;
        #pragma unroll
        for (int idx = 0; idx < 4; idx++) {
            int jp = (idx < s) ? idx : 256 + idx;
            g_xc4[((ai * 4 + s) * AA + aa2) * XSTR + jp] = 0.f;
        }
    }
}

// ---------------- merged correlation kernel (fm + xcorr), f32x2 ------------
// blk <  1024 : fm    (row 0..3, tile 0..127, half 0..1) -> g_fm + colmax
// blk >= 1024 : xcorr (row 0..127, tile 0..1, half 0..1) -> g_xc4 (4 shifts)
__global__ __launch_bounds__(256) void corr_kernel()
{
    __shared__ float s_du[KK][64];   // [k][a_local] 32KB
    __shared__ float s_sig[256];
    __shared__ float s_red[8][128];  // colmax epilogue

    int blk = blockIdx.x;
    int tid = threadIdx.x; // 256

    int mode, row, tile, half;
    if (blk < 1024) { mode = 0; half = blk & 1; row = (blk >> 1) & 3; tile = blk >> 3; }
    else { int b2 = blk - 1024; mode = 1; half = b2 & 1; tile = (b2 >> 1) & 1; row = b2 >> 2; }
    int t0 = tile * 128;

    for (int i = tid; i < 64 * KK; i += 256) {
        int al = i >> 7, k = i & 127;
        s_du[k][al] = g_du[(half * 64 + al) * KK + k];
    }

    const float* src;
    int srcLen, shift;
    if (mode == 0) { src = g_res + row * TT; srcLen = TT; shift = 64; }
    else           { src = g_du + row * KK;  srcLen = KK; shift = 127; }

    {
        int t = t0 + tid - shift;
        s_sig[tid] = (t >= 0 && t < srcLen) ? src[t] : 0.f;
    }
    __syncthreads();

    int x = tid & 31, y = tid >> 5;
    int c0 = x * 4, a0 = y * 8;

    unsigned long long acc2[4][4];
    #pragma unroll
    for (int j = 0; j < 4; j++)
        #pragma unroll
        for (int c = 0; c < 4; c++) acc2[j][c] = 0ull;

    // loop-carried packed broadcast regs
    unsigned long long rr0, rr1, rr2, rr3;
    {
        unsigned u0 = __float_as_uint(s_sig[c0]);
        unsigned u1 = __float_as_uint(s_sig[c0 + 1]);
        unsigned u2 = __float_as_uint(s_sig[c0 + 2]);
        unsigned u3 = __float_as_uint(s_sig[c0 + 3]);
        asm("mov.b64 %0, {%1, %1};" : "=l"(rr0) : "r"(u0));
        asm("mov.b64 %0, {%1, %1};" : "=l"(rr1) : "r"(u1));
        asm("mov.b64 %0, {%1, %1};" : "=l"(rr2) : "r"(u2));
        asm("mov.b64 %0, {%1, %1};" : "=l"(rr3) : "r"(u3));
    }

    #pragma unroll 4
    for (int k = 0; k < KK; k++) {
        ulonglong2 p0 = *(const ulonglong2*)&s_du[k][a0];
        ulonglong2 p1 = *(const ulonglong2*)&s_du[k][a0 + 4];
        unsigned long long dv[4] = { p0.x, p0.y, p1.x, p1.y };

        #pragma unroll
        for (int j = 0; j < 4; j++) {
            asm("fma.rn.f32x2 %0, %1, %2, %0;" : "+l"(acc2[j][0]) : "l"(dv[j]), "l"(rr0));
            asm("fma.rn.f32x2 %0, %1, %2, %0;" : "+l"(acc2[j][1]) : "l"(dv[j]), "l"(rr1));
            asm("fma.rn.f32x2 %0, %1, %2, %0;" : "+l"(acc2[j][2]) : "l"(dv[j]), "l"(rr2));
            asm("fma.rn.f32x2 %0, %1, %2, %0;" : "+l"(acc2[j][3]) : "l"(dv[j]), "l"(rr3));
        }
        rr0 = rr1; rr1 = rr2; rr2 = rr3;
        unsigned rn = __float_as_uint(s_sig[c0 + 4 + k]);  // max idx 255, in bounds
        asm("mov.b64 %0, {%1, %1};" : "=l"(rr3) : "r"(rn));
    }

    int a_base = half * 64 + a0;
    int t = t0 + c0;

    if (mode == 0) {
        float* out = g_fm + row * AA * TT;
        float cmax[4] = { -3.402823466e38f, -3.402823466e38f,
                          -3.402823466e38f, -3.402823466e38f };
        #pragma unroll
        for (int j = 0; j < 4; j++) {
            float lo[4], hi[4];
            #pragma unroll
            for (int c = 0; c < 4; c++) {
                lo[c] = __uint_as_float((unsigned)acc2[j][c]);
                hi[c] = __uint_as_float((unsigned)(acc2[j][c] >> 32));
                cmax[c] = fmaxf(cmax[c], fmaxf(lo[c], hi[c]));
            }
            *(float4*)(out + (a_base + 2 * j) * TT + t) =
                make_float4(lo[0], lo[1], lo[2], lo[3]);
            *(float4*)(out + (a_base + 2 * j + 1) * TT + t) =
                make_float4(hi[0], hi[1], hi[2], hi[3]);
        }
        #pragma unroll
        for (int c = 0; c < 4; c++) s_red[y][c0 + c] = cmax[c];
        __syncthreads();
        if (tid < 128) {
            float m = s_red[0][tid];
            #pragma unroll
            for (int w = 1; w < 8; w++) m = fmaxf(m, s_red[w][tid]);
            atomicMax(&g_cm[row * TT + t0 + tid], fenc(m));
        }
    } else {
        // write 4 shifted copies: g_xc4[row][s][a][j + s] = xcorr[row][a][j]
        #pragma unroll
        for (int j = 0; j < 4; j++) {
            #pragma unroll
            for (int c = 0; c < 4; c++) {
                float lov = __uint_as_float((unsigned)acc2[j][c]);
                float hiv = __uint_as_float((unsigned)(acc2[j][c] >> 32));
                int jj = t + c;
                #pragma unroll
                for (int s = 0; s < 4; s++) {
                    long base = ((long)(row * 4 + s) * AA + a_base + 2 * j) * XSTR + jj + s;
                    g_xc4[base] = lov;
                    g_xc4[base + XSTR] = hiv;
                }
            }
        }
    }
}

// ---- helpers for steps kernel ----------------------------------------------

// column-quad max over all 128 atoms; atoms across lanes (stride 65 f4 ≡ 1 mod 8
// -> conflict-free LDS.128); 5-level butterfly; lanes 0-3 store.
// Warp-uniform: ALL 32 lanes must call this.
__device__ __forceinline__ void colmax_quad(const float* s_tile, unsigned* s_cm,
                                            int w0, int q, int lane)
{
    float4 x0 = *(const float4*)(s_tile + lane * XSTR + 4 * q);
    float4 x1 = *(const float4*)(s_tile + (lane + 32) * XSTR + 4 * q);
    float4 x2 = *(const float4*)(s_tile + (lane + 64) * XSTR + 4 * q);
    float4 x3 = *(const float4*)(s_tile + (lane + 96) * XSTR + 4 * q);
    float m0 = fmaxf(fmaxf(x0.x, x1.x), fmaxf(x2.x, x3.x));
    float m1 = fmaxf(fmaxf(x0.y, x1.y), fmaxf(x2.y, x3.y));
    float m2 = fmaxf(fmaxf(x0.z, x1.z), fmaxf(x2.z, x3.z));
    float m3 = fmaxf(fmaxf(x0.w, x1.w), fmaxf(x2.w, x3.w));
    #pragma unroll
    for (int off = 16; off; off >>= 1) {
        m0 = fmaxf(m0, __shfl_xor_sync(0xffffffffu, m0, off));
        m1 = fmaxf(m1, __shfl_xor_sync(0xffffffffu, m1, off));
        m2 = fmaxf(m2, __shfl_xor_sync(0xffffffffu, m2, off));
        m3 = fmaxf(m3, __shfl_xor_sync(0xffffffffu, m3, off));
    }
    if (lane < 4) {
        float mv = (lane == 0) ? m0 : (lane == 1) ? m1 : (lane == 2) ? m2 : m3;
        int t = w0 + 4 * q + lane;
        if (t >= 0 && t < TT) s_cm[t] = fenc(mv);
    }
}

// segment max over 64 cols; 4 cooperating threads (same warp, part = lane&3).
// Warp-uniform: ALL lanes of the calling warp must execute (pass valid=false
// for lanes that should not store; they still do the loads+shuffles).
__device__ __forceinline__ void seg_update(const unsigned* s_cm, unsigned* s_seg,
                                           int seg, int part, bool valid)
{
    const uint4* p = (const uint4*)(s_cm + (seg << 6) + (part << 4));
    unsigned m = 0u;
    #pragma unroll
    for (int i = 0; i < 4; i++) {
        uint4 u = p[i];
        unsigned a = (u.x > u.y) ? u.x : u.y;
        unsigned b = (u.z > u.w) ? u.z : u.w;
        unsigned c = (a > b) ? a : b;
        if (c > m) m = c;
    }
    {
        unsigned o = __shfl_xor_sync(0xffffffffu, m, 1);
        if (o > m) m = o;
        o = __shfl_xor_sync(0xffffffffu, m, 2);
        if (o > m) m = o;
    }
    if (valid && part == 0) s_seg[seg] = m;
}

// ---------------- all 16 matched-pursuit steps + fused final ---------------
// dynamic smem: s_cm (TT u32, 64KB) + s_tile (AA*XSTR floats, 133KB)
__global__ __launch_bounds__(1024) void steps_kernel(const float* __restrict__ atom_emb,
                                                     const float* __restrict__ proj,
                                                     float* __restrict__ out)
{
    extern __shared__ unsigned char smem_raw[];
    unsigned* s_cm   = (unsigned*)smem_raw;
    float*    s_tile = (float*)(smem_raw + TT * 4);

    __shared__ unsigned s_seg[256];   // 64-col segment maxima
    __shared__ float    s_nred[32];
    __shared__ float sh_v;
    __shared__ int   sh_ti, sh_ai, sh_pa, sh_aa;
    __shared__ int   s_last;
    __shared__ float s_keys[64];
    __shared__ int   s_order[64];
    __shared__ float s_proj[128];

    int r = blockIdx.x;
    int tid = threadIdx.x;
    int lane = tid & 31, wid = tid >> 5;

    float* fmr  = g_fm  + r * AA * TT;
    float* resr = g_res + r * TT;

    // load initial colmax into smem
    #pragma unroll
    for (int q = 0; q < 4; q++)
        ((uint4*)s_cm)[tid + 1024 * q] = ((const uint4*)(g_cm + r * TT))[tid + 1024 * q];
    __syncthreads();

    // build segment maxima (256 segs x 4 threads; all warps fully active)
    seg_update(s_cm, s_seg, tid >> 2, tid & 3, true);
    __syncthreads();

    for (int step = 0; step < NSTEP; step++) {
        // --- phase 1 (warp 0 only): seg argmax -> in-seg scan -> atom scan ---
        if (wid == 0) {
            unsigned bk = 0u; int bs = 0;
            #pragma unroll
            for (int q = 0; q < 8; q++) {
                int s = lane + 32 * q;
                unsigned vv = s_seg[s];
                if (vv > bk) { bk = vv; bs = s; }
            }
            #pragma unroll
            for (int off = 16; off; off >>= 1) {
                unsigned ok = __shfl_down_sync(0xffffffffu, bk, off);
                int      os = __shfl_down_sync(0xffffffffu, bs, off);
                if (ok > bk || (ok == bk && os < bs)) { bk = ok; bs = os; }
            }
            bs = __shfl_sync(0xffffffffu, bs, 0);

            int base = bs << 6;
            unsigned ck = 0u; int ct = base;
            {
                unsigned v0 = s_cm[base + lane];
                unsigned v1 = s_cm[base + 32 + lane];
                if (v0 > ck) { ck = v0; ct = base + lane; }
                if (v1 > ck) { ck = v1; ct = base + 32 + lane; }
            }
            #pragma unroll
            for (int off = 16; off; off >>= 1) {
                unsigned ok = __shfl_down_sync(0xffffffffu, ck, off);
                int      ot = __shfl_down_sync(0xffffffffu, ct, off);
                if (ok > ck || (ok == ck && ot < ct)) { ck = ok; ct = ot; }
            }
            ct = __shfl_sync(0xffffffffu, ct, 0);

            // atom argmax at winning column (gmem, L2-hot)
            float av = -3.402823466e38f;
            int aarg = 0x7fffffff;
            #pragma unroll
            for (int a4 = 0; a4 < 4; a4++) {
                int a = lane + 32 * a4;
                float fv = fmr[a * TT + ct];
                if (fv > av) { av = fv; aarg = a; }
            }
            #pragma unroll
            for (int off = 16; off; off >>= 1) {
                float ov = __shfl_down_sync(0xffffffffu, av, off);
                int   oa = __shfl_down_sync(0xffffffffu, aarg, off);
                if (ov > av || (ov == av && oa < aarg)) { av = ov; aarg = oa; }
            }
            if (lane == 0) {
                sh_v = av; sh_ti = ct; sh_ai = aarg;
                int pa, aa2;
                if (av > 0.f)      { pa = ct; aa2 = aarg; }
                else if (av < 0.f) { pa = (ct == 0) ? 1 : 0; aa2 = (aarg == 0) ? 1 : 0; }
                else               { pa = 0; aa2 = 0; }
                sh_pa = pa; sh_aa = aa2;
            }
        }
        __syncthreads();

        float v = sh_v;
        int ti = sh_ti, ai = sh_ai;
        int w0  = (ti - 127) & ~3;        // aligned window start
        int shf = (ti - 127) - w0;        // 0..3

        // --- phase 3a: embedding + residual update ---
        if (tid < 128) {
            float e;
            if (tid == 0)      e = (float)sh_pa * (20.f / (float)(TT - 1));
            else if (tid == 1) e = v;
            else               e = atom_emb[sh_aa * EE + (tid - 2)];
            g_emb[(r * NSTEP + step) * 128 + tid] = e;
        } else if (tid < 256) {
            int k = tid - 128;
            int t = ti - 64 + k;
            if (t >= 0 && t < TT) resr[t] -= v * g_du[ai * KK + k];
        }

        // --- phase 3b: coalesced float4 window update (fm gmem + smem tile)
        {
            #pragma unroll
            for (int ii = 0; ii < 4; ii++) {
                int a = wid * 4 + ii;
                float*       fp = fmr + a * TT;
                const float* xp = g_xc4 + ((long)(ai * 4 + shf) * AA + a) * XSTR;
                float*       tp = s_tile + a * XSTR;
                #pragma unroll
                for (int it = 0; it < 3; it++) {
                    int jj4 = lane + 32 * it;
                    if (jj4 < 65) {
                        int jp = jj4 * 4;
                        int t = w0 + jp;
                        if (t >= 0 && t + 3 < TT) {
                            float4 f = *(const float4*)(fp + t);
                            float4 xx = *(const float4*)(xp + jp);
                            f.x -= v * xx.x; f.y -= v * xx.y;
                            f.z -= v * xx.z; f.w -= v * xx.w;
                            *(float4*)(fp + t) = f;
                            *(float4*)(tp + jp) = f;
                        } else {
                            #pragma unroll
                            for (int e = 0; e < 4; e++) {
                                int te = t + e;
                                if (te >= 0 && te < TT) {
                                    float f = fp[te] - v * xp[jp + e];
                                    fp[te] = f;
                                    tp[jp + e] = f;
                                }
                            }
                        }
                    }
                }
            }
        }
        __syncthreads();

        // --- phase 4: warp-owned colmax recompute (no atomics) ---
        colmax_quad(s_tile, s_cm, w0, wid * 2,     lane);
        colmax_quad(s_tile, s_cm, w0, wid * 2 + 1, lane);
        if (wid == 0) colmax_quad(s_tile, s_cm, w0, 64, lane);
        __syncthreads();

        // --- phase 5: refresh affected segment maxima (<= 6 segs) ----------
        // warp 0 only; ALL 32 lanes execute seg_update (invalid lanes redo
        // segment s_lo without storing) so the shuffles stay warp-uniform.
        if (wid == 0) {
            int s_lo = (w0 > 0 ? w0 : 0) >> 6;
            int hi_t = w0 + 259; if (hi_t > TT - 1) hi_t = TT - 1;
            int s_hi = hi_t >> 6;
            int seg = s_lo + (lane >> 2);
            bool valid = (lane < 24) && (seg <= s_hi);
            int segc = valid ? seg : s_lo;
            seg_update(s_cm, s_seg, segc, lane & 3, valid);
        }
        __syncthreads();
    }

    // --- residual norm (fused) ---
    float ss = 0.f;
    #pragma unroll
    for (int q = 0; q < 4; q++) {
        float4 vv = ((const float4*)resr)[tid + 1024 * q];
        ss += vv.x * vv.x + vv.y * vv.y + vv.z * vv.z + vv.w * vv.w;
    }
    #pragma unroll
    for (int off = 16; off; off >>= 1)
        ss += __shfl_down_sync(0xffffffffu, ss, off);
    if (lane == 0) s_nred[wid] = ss;
    __syncthreads();
    if (wid == 0) {
        float t2 = s_nred[lane];
        #pragma unroll
        for (int off = 16; off; off >>= 1)
            t2 += __shfl_down_sync(0xffffffffu, t2, off);
        if (lane == 0) g_norm[r] = sqrtf(t2);
    }

    // --- fused final loss: last block to finish computes it ---
    __threadfence();
    __syncthreads();
    if (tid == 0) s_last = (atomicAdd(&g_done, 1) == NROW - 1);
    __syncthreads();
    if (!s_last) return;
    __threadfence();

    if (tid < 128) s_proj[tid] = proj[tid];
    __syncthreads();

    // keys: 32 warps x 2 keys (16 lanes per key)
    {
        int key = wid * 2 + (lane >> 4);
        int sl = lane & 15;
        const float* e = g_emb + key * 128;
        float p = 0.f;
        #pragma unroll
        for (int q = 0; q < 8; q++) {
            int j = sl + 16 * q;
            p += e[j] * s_proj[j];
        }
        #pragma unroll
        for (int off = 1; off < 16; off <<= 1)
            p += __shfl_xor_sync(0xffffffffu, p, off);
        if (sl == 0) s_keys[key] = p;
    }
    __syncthreads();

    if (tid < 4) {   // stable insertion sort, ascending (matches jnp.argsort)
        int ord[16];
        for (int i = 0; i < 16; i++) ord[i] = i;
        for (int i = 1; i < 16; i++) {
            int oi = ord[i];
            float ki = s_keys[tid * 16 + oi];
            int j = i - 1;
            while (j >= 0 && s_keys[tid * 16 + ord[j]] > ki) { ord[j + 1] = ord[j]; j--; }
            ord[j + 1] = oi;
        }
        for (int i = 0; i < 16; i++) s_order[tid * 16 + i] = ord[i];
    }
    __syncthreads();

    float acc = 0.f;
    #pragma unroll
    for (int q = 0; q < 4; q++) {
        int i = tid + 1024 * q;
        int bb = i >> 11;
        int st = (i >> 7) & 15;
        int e = i & 127;
        int sa = s_order[bb * 16 + st];
        int sb = s_order[(2 + bb) * 16 + st];
        float dd = g_emb[(bb * 16 + sa) * 128 + e] - g_emb[((2 + bb) * 16 + sb) * 128 + e];
        acc += dd * dd;
    }
    #pragma unroll
    for (int off = 16; off; off >>= 1)
        acc += __shfl_down_sync(0xffffffffu, acc, off);
    if (lane == 0) s_nred[wid] = acc;
    __syncthreads();
    if (tid == 0) {
        float t2 = 0.f;
        for (int w = 0; w < 32; w++) t2 += s_nred[w];
        out[0] = t2 / 4096.f
               + 0.5f * (fabsf(g_norm[0] - g_norm[2]) + fabsf(g_norm[1] - g_norm[3]));
    }
}

// ---------------- launch ----------------------------------------------------
#define SMEM_STEPS (TT * 4 + AA * XSTR * 4)  // 65536 + 133120 = 198656

extern "C" void kernel_launch(void* const* d_in, const int* in_sizes, int n_in,
                              void* d_out, int out_size)
{
    (void)in_sizes; (void)n_in; (void)out_size;
    const float* a    = (const float*)d_in[0];
    const float* b    = (const float*)d_in[1];
    const float* d    = (const float*)d_in[2];
    const float* aemb = (const float*)d_in[3];
    const float* proj = (const float*)d_in[4];
    float* out = (float*)d_out;

    cudaFuncSetAttribute(steps_kernel,
                         cudaFuncAttributeMaxDynamicSharedMemorySize, SMEM_STEPS);

    prep_kernel<<<896, 128>>>(a, b, d);
    corr_kernel<<<1536, 256>>>();                 // fm (1024) + xcorr->xc4 (512)
    steps_kernel<<<4, 1024, SMEM_STEPS>>>(aemb, proj, out);
}

// round 9
// speedup vs baseline: 1.2429x; 1.0585x over previous
#include <cuda_runtime.h>
#include <math.h>

#define TT    16384
#define AA    128
#define KK    128
#define NROW  4
#define NSTEP 16
#define EE    126
#define XSTR  260      // padded xc4 row stride in floats (multiple of 4)

// ---------------- device scratch (static: no allocations allowed) ----------
__device__ __align__(16) float    g_du[AA * KK];
__device__ __align__(16) float    g_xc4[AA * 4 * AA * XSTR]; // ~68MB
__device__ __align__(16) float    g_fm[NROW * AA * TT];
__device__ __align__(16) float    g_res[NROW * TT];
__device__ __align__(16) unsigned g_cm[NROW * TT];           // encoded colmax
__device__ __align__(16) float    g_emb[NROW * NSTEP * 128];
__device__ float                  g_norm[NROW];
__device__ int                    g_done;

// order-preserving float->uint encoding (monotone bijection)
__device__ __forceinline__ unsigned fenc(float f) {
    unsigned u = __float_as_uint(f);
    return (u & 0x80000000u) ? ~u : (u | 0x80000000u);
}

// ---------------- prep: d_unit + residual/cm init + xc4 edge zero ----------
__global__ void prep_kernel(const float* __restrict__ a,
                            const float* __restrict__ b,
                            const float* __restrict__ d)
{
    __shared__ float sred[4];
    int bx = blockIdx.x;
    int tid = threadIdx.x; // 128
    if (bx == 0 && tid == 0) g_done = 0;
    if (bx < AA) {
        float v = d[bx * KK + tid];
        float ss = v * v;
        #pragma unroll
        for (int off = 16; off; off >>= 1)
            ss += __shfl_down_sync(0xffffffffu, ss, off);
        if ((tid & 31) == 0) sred[tid >> 5] = ss;
        __syncthreads();
        float tot = sred[0] + sred[1] + sred[2] + sred[3];
        g_du[bx * KK + tid] = v / (sqrtf(tot) + 1e-8f);
    } else if (bx < 384) {
        int base = (bx - AA) * 256;
        #pragma unroll
        for (int j = tid; j < 256; j += 128) {
            int i = base + j;
            g_res[i] = (i < 2 * TT) ? a[i] : b[i - 2 * TT];
            g_cm[i] = 0u;
        }
    } else {
        // zero uncovered edges of g_xc4: for shift s, cols [0,s) and [256+s,260)
        int bb = bx - 384;           // 0..511
        int ai = bb >> 2, s = bb & 3;
        int aa2 = tid;
        #pragma unroll
        for (int idx = 0; idx < 4; idx++) {
            int jp = (idx < s) ? idx : 256 + idx;
            g_xc4[((ai * 4 + s) * AA + aa2) * XSTR + jp] = 0.f;
        }
    }
}

// ---------------- correlation kernel (round-3 inner loop), f32x2 -----------
// mode 0: fm    (1024 blocks: row 0..3, tile 0..127, half 0..1) -> g_fm + colmax
// mode 1: xcorr (512 blocks:  row 0..127, tile 0..1, half 0..1) -> g_xc4 (4 shifts)
__global__ __launch_bounds__(256) void corr_kernel(int mode)
{
    __shared__ float s_du[KK][64];   // [k][a_local] 32KB
    __shared__ float s_sig[256];
    __shared__ float s_red[8][128];  // colmax epilogue

    int blk = blockIdx.x;
    int tid = threadIdx.x; // 256

    int row, tile, half;
    if (mode == 0) { half = blk & 1; row = (blk >> 1) & 3; tile = blk >> 3; }
    else           { half = blk & 1; tile = (blk >> 1) & 1; row = blk >> 2; }
    int t0 = tile * 128;

    for (int i = tid; i < 64 * KK; i += 256) {
        int al = i >> 7, k = i & 127;
        s_du[k][al] = g_du[(half * 64 + al) * KK + k];
    }

    const float* src;
    int srcLen, shift;
    if (mode == 0) { src = g_res + row * TT; srcLen = TT; shift = 64; }
    else           { src = g_du + row * KK;  srcLen = KK; shift = 127; }

    {
        int t = t0 + tid - shift;
        s_sig[tid] = (t >= 0 && t < srcLen) ? src[t] : 0.f;
    }
    __syncthreads();

    int x = tid & 31, y = tid >> 5;
    int c0 = x * 4, a0 = y * 8;

    unsigned long long acc2[4][4];
    #pragma unroll
    for (int j = 0; j < 4; j++)
        #pragma unroll
        for (int c = 0; c < 4; c++) acc2[j][c] = 0ull;

    unsigned r0 = __float_as_uint(s_sig[c0]);
    unsigned r1 = __float_as_uint(s_sig[c0 + 1]);
    unsigned r2 = __float_as_uint(s_sig[c0 + 2]);
    unsigned r3 = __float_as_uint(s_sig[c0 + 3]);

    #pragma unroll 4
    for (int k = 0; k < KK; k++) {
        unsigned long long dv[4];
        #pragma unroll
        for (int j = 0; j < 4; j++)
            dv[j] = *(const unsigned long long*)&s_du[k][a0 + 2 * j];

        unsigned long long rr0, rr1, rr2, rr3;
        asm("mov.b64 %0, {%1, %1};" : "=l"(rr0) : "r"(r0));
        asm("mov.b64 %0, {%1, %1};" : "=l"(rr1) : "r"(r1));
        asm("mov.b64 %0, {%1, %1};" : "=l"(rr2) : "r"(r2));
        asm("mov.b64 %0, {%1, %1};" : "=l"(rr3) : "r"(r3));

        #pragma unroll
        for (int j = 0; j < 4; j++) {
            asm("fma.rn.f32x2 %0, %1, %2, %0;" : "+l"(acc2[j][0]) : "l"(dv[j]), "l"(rr0));
            asm("fma.rn.f32x2 %0, %1, %2, %0;" : "+l"(acc2[j][1]) : "l"(dv[j]), "l"(rr1));
            asm("fma.rn.f32x2 %0, %1, %2, %0;" : "+l"(acc2[j][2]) : "l"(dv[j]), "l"(rr2));
            asm("fma.rn.f32x2 %0, %1, %2, %0;" : "+l"(acc2[j][3]) : "l"(dv[j]), "l"(rr3));
        }
        r0 = r1; r1 = r2; r2 = r3;
        r3 = __float_as_uint(s_sig[c0 + 4 + k]);   // max index 255, in bounds
    }

    int a_base = half * 64 + a0;
    int t = t0 + c0;

    if (mode == 0) {
        float* out = g_fm + row * AA * TT;
        float cmax[4] = { -3.402823466e38f, -3.402823466e38f,
                          -3.402823466e38f, -3.402823466e38f };
        #pragma unroll
        for (int j = 0; j < 4; j++) {
            float lo[4], hi[4];
            #pragma unroll
            for (int c = 0; c < 4; c++) {
                lo[c] = __uint_as_float((unsigned)acc2[j][c]);
                hi[c] = __uint_as_float((unsigned)(acc2[j][c] >> 32));
                cmax[c] = fmaxf(cmax[c], fmaxf(lo[c], hi[c]));
            }
            *(float4*)(out + (a_base + 2 * j) * TT + t) =
                make_float4(lo[0], lo[1], lo[2], lo[3]);
            *(float4*)(out + (a_base + 2 * j + 1) * TT + t) =
                make_float4(hi[0], hi[1], hi[2], hi[3]);
        }
        #pragma unroll
        for (int c = 0; c < 4; c++) s_red[y][c0 + c] = cmax[c];
        __syncthreads();
        if (tid < 128) {
            float m = s_red[0][tid];
            #pragma unroll
            for (int w = 1; w < 8; w++) m = fmaxf(m, s_red[w][tid]);
            atomicMax(&g_cm[row * TT + t0 + tid], fenc(m));
        }
    } else {
        // write 4 shifted copies: g_xc4[row][s][a][j + s] = xcorr[row][a][j]
        #pragma unroll
        for (int j = 0; j < 4; j++) {
            #pragma unroll
            for (int c = 0; c < 4; c++) {
                float lov = __uint_as_float((unsigned)acc2[j][c]);
                float hiv = __uint_as_float((unsigned)(acc2[j][c] >> 32));
                int jj = t + c;
                #pragma unroll
                for (int s = 0; s < 4; s++) {
                    long base = ((long)(row * 4 + s) * AA + a_base + 2 * j) * XSTR + jj + s;
                    g_xc4[base] = lov;
                    g_xc4[base + XSTR] = hiv;
                }
            }
        }
    }
}

// ---------------- all 16 matched-pursuit steps + fused final ---------------
// dynamic smem: s_cm (TT u32, 64KB) + s_tile (AA*XSTR floats, 133KB)
// (steps body identical to the measured-best round-3 version)
__global__ __launch_bounds__(1024) void steps_kernel(const float* __restrict__ atom_emb,
                                                     const float* __restrict__ proj,
                                                     float* __restrict__ out)
{
    extern __shared__ unsigned char smem_raw[];
    unsigned* s_cm   = (unsigned*)smem_raw;
    float*    s_tile = (float*)(smem_raw + TT * 4);

    __shared__ unsigned s_rk[32];
    __shared__ int      s_rt[32];
    __shared__ float    s_nred[32];
    __shared__ float sh_v;
    __shared__ int   sh_ti, sh_ai, sh_pa, sh_aa;
    __shared__ int   s_last;
    __shared__ float s_keys[64];
    __shared__ int   s_order[64];
    __shared__ float s_proj[128];

    int r = blockIdx.x;
    int tid = threadIdx.x;
    int lane = tid & 31, wid = tid >> 5;

    float* fmr  = g_fm  + r * AA * TT;
    float* resr = g_res + r * TT;

    // load initial colmax into smem
    #pragma unroll
    for (int q = 0; q < 4; q++)
        ((uint4*)s_cm)[tid + 1024 * q] = ((const uint4*)(g_cm + r * TT))[tid + 1024 * q];
    __syncthreads();

    for (int step = 0; step < NSTEP; step++) {
        // --- phase 1: global argmax over encoded s_cm (tie -> lowest t) ---
        unsigned bk = 0u;
        int bt = 0x7fffffff;
        #pragma unroll
        for (int q = 0; q < 4; q++) {
            uint4 u = ((const uint4*)s_cm)[tid + 1024 * q];
            int tb = (tid + 1024 * q) * 4;
            if (u.x > bk) { bk = u.x; bt = tb; }
            if (u.y > bk) { bk = u.y; bt = tb + 1; }
            if (u.z > bk) { bk = u.z; bt = tb + 2; }
            if (u.w > bk) { bk = u.w; bt = tb + 3; }
        }
        #pragma unroll
        for (int off = 16; off; off >>= 1) {
            unsigned ok = __shfl_down_sync(0xffffffffu, bk, off);
            int      ot = __shfl_down_sync(0xffffffffu, bt, off);
            if (ok > bk || (ok == bk && ot < bt)) { bk = ok; bt = ot; }
        }
        if (lane == 0) { s_rk[wid] = bk; s_rt[wid] = bt; }
        __syncthreads();

        // --- phase 2: warp 0 final reduce + atom argmax at winning column ---
        if (wid == 0) {
            bk = s_rk[lane]; bt = s_rt[lane];
            #pragma unroll
            for (int off = 16; off; off >>= 1) {
                unsigned ok = __shfl_down_sync(0xffffffffu, bk, off);
                int      ot = __shfl_down_sync(0xffffffffu, bt, off);
                if (ok > bk || (ok == bk && ot < bt)) { bk = ok; bt = ot; }
            }
            bt = __shfl_sync(0xffffffffu, bt, 0);

            float av = -3.402823466e38f;
            int aarg = 0x7fffffff;
            #pragma unroll
            for (int a = lane; a < AA; a += 32) {
                float fv = fmr[a * TT + bt];
                if (fv > av) { av = fv; aarg = a; }
            }
            #pragma unroll
            for (int off = 16; off; off >>= 1) {
                float ov = __shfl_down_sync(0xffffffffu, av, off);
                int   oa = __shfl_down_sync(0xffffffffu, aarg, off);
                if (ov > av || (ov == av && oa < aarg)) { av = ov; aarg = oa; }
            }
            if (lane == 0) {
                sh_v = av; sh_ti = bt; sh_ai = aarg;
                int pa, aa2;
                if (av > 0.f)      { pa = bt; aa2 = aarg; }
                else if (av < 0.f) { pa = (bt == 0) ? 1 : 0; aa2 = (aarg == 0) ? 1 : 0; }
                else               { pa = 0; aa2 = 0; }
                sh_pa = pa; sh_aa = aa2;
            }
        }
        __syncthreads();

        float v = sh_v;
        int ti = sh_ti, ai = sh_ai;
        int w0  = (ti - 127) & ~3;        // aligned window start
        int shf = (ti - 127) - w0;        // 0..3

        // --- phase 3a: embedding + residual update + s_cm window reset ---
        if (tid < 128) {
            float e;
            if (tid == 0)      e = (float)sh_pa * (20.f / (float)(TT - 1));
            else if (tid == 1) e = v;
            else               e = atom_emb[sh_aa * EE + (tid - 2)];
            g_emb[(r * NSTEP + step) * 128 + tid] = e;
        } else if (tid < 256) {
            int k = tid - 128;
            int t = ti - 64 + k;
            if (t >= 0 && t < TT) resr[t] -= v * g_du[ai * KK + k];
        } else if (tid < 516) {
            int c = tid - 256;            // 0..259
            int t = w0 + c;
            if (t >= 0 && t < TT) s_cm[t] = 0u;
        }

        // --- phase 3b: coalesced float4 window update (fm gmem + smem tile)
        {
            #pragma unroll
            for (int ii = 0; ii < 4; ii++) {
                int a = wid * 4 + ii;
                float*       fp = fmr + a * TT;
                const float* xp = g_xc4 + ((long)(ai * 4 + shf) * AA + a) * XSTR;
                float*       tp = s_tile + a * XSTR;
                #pragma unroll
                for (int it = 0; it < 3; it++) {
                    int jj4 = lane + 32 * it;
                    if (jj4 < 65) {
                        int jp = jj4 * 4;
                        int t = w0 + jp;
                        if (t >= 0 && t + 3 < TT) {
                            float4 f = *(const float4*)(fp + t);
                            float4 xx = *(const float4*)(xp + jp);
                            f.x -= v * xx.x; f.y -= v * xx.y;
                            f.z -= v * xx.z; f.w -= v * xx.w;
                            *(float4*)(fp + t) = f;
                            *(float4*)(tp + jp) = f;
                        } else {
                            #pragma unroll
                            for (int e = 0; e < 4; e++) {
                                int te = t + e;
                                if (te >= 0 && te < TT) {
                                    float f = fp[te] - v * xp[jp + e];
                                    fp[te] = f;
                                    tp[jp + e] = f;
                                }
                            }
                        }
                    }
                }
            }
        }
        __syncthreads();

        // --- phase 4: colmax partials + u32 smem atomicMax (round-3) -------
        {
            int c4 = tid & 63, sub = tid >> 6;      // 16 subs x 8 atoms
            #pragma unroll
            for (int pass = 0; pass < 2; pass++) {
                int cc4, ss;
                if (pass == 0) { cc4 = c4; ss = sub; }
                else { if (tid >= 16) break; cc4 = 64; ss = tid; }
                float m0 = -3.402823466e38f, m1 = m0, m2 = m0, m3 = m0;
                #pragma unroll
                for (int i = 0; i < 8; i++) {
                    int a = ss * 8 + i;
                    float4 xx = *(const float4*)(s_tile + a * XSTR + 4 * cc4);
                    m0 = fmaxf(m0, xx.x); m1 = fmaxf(m1, xx.y);
                    m2 = fmaxf(m2, xx.z); m3 = fmaxf(m3, xx.w);
                }
                int tb = w0 + 4 * cc4;
                if (tb >= 0     && tb < TT)     atomicMax(&s_cm[tb],     fenc(m0));
                if (tb + 1 >= 0 && tb + 1 < TT) atomicMax(&s_cm[tb + 1], fenc(m1));
                if (tb + 2 >= 0 && tb + 2 < TT) atomicMax(&s_cm[tb + 2], fenc(m2));
                if (tb + 3 >= 0 && tb + 3 < TT) atomicMax(&s_cm[tb + 3], fenc(m3));
            }
        }
        __syncthreads();
    }

    // --- residual norm (fused) ---
    float ss = 0.f;
    #pragma unroll
    for (int q = 0; q < 4; q++) {
        float4 vv = ((const float4*)resr)[tid + 1024 * q];
        ss += vv.x * vv.x + vv.y * vv.y + vv.z * vv.z + vv.w * vv.w;
    }
    #pragma unroll
    for (int off = 16; off; off >>= 1)
        ss += __shfl_down_sync(0xffffffffu, ss, off);
    if (lane == 0) s_nred[wid] = ss;
    __syncthreads();
    if (wid == 0) {
        float t2 = s_nred[lane];
        #pragma unroll
        for (int off = 16; off; off >>= 1)
            t2 += __shfl_down_sync(0xffffffffu, t2, off);
        if (lane == 0) g_norm[r] = sqrtf(t2);
    }

    // --- fused final loss: last block to finish computes it ---
    __threadfence();
    __syncthreads();
    if (tid == 0) s_last = (atomicAdd(&g_done, 1) == NROW - 1);
    __syncthreads();
    if (!s_last) return;
    __threadfence();

    if (tid < 128) s_proj[tid] = proj[tid];
    __syncthreads();

    // keys: 32 warps x 2 keys (16 lanes per key)
    {
        int key = wid * 2 + (lane >> 4);
        int sl = lane & 15;
        const float* e = g_emb + key * 128;
        float p = 0.f;
        #pragma unroll
        for (int q = 0; q < 8; q++) {
            int j = sl + 16 * q;
            p += e[j] * s_proj[j];
        }
        #pragma unroll
        for (int off = 1; off < 16; off <<= 1)
            p += __shfl_xor_sync(0xffffffffu, p, off);
        if (sl == 0) s_keys[key] = p;
    }
    __syncthreads();

    if (tid < 4) {   // stable insertion sort, ascending (matches jnp.argsort)
        int ord[16];
        for (int i = 0; i < 16; i++) ord[i] = i;
        for (int i = 1; i < 16; i++) {
            int oi = ord[i];
            float ki = s_keys[tid * 16 + oi];
            int j = i - 1;
            while (j >= 0 && s_keys[tid * 16 + ord[j]] > ki) { ord[j + 1] = ord[j]; j--; }
            ord[j + 1] = oi;
        }
        for (int i = 0; i < 16; i++) s_order[tid * 16 + i] = ord[i];
    }
    __syncthreads();

    float acc = 0.f;
    #pragma unroll
    for (int q = 0; q < 4; q++) {
        int i = tid + 1024 * q;
        int bb = i >> 11;
        int st = (i >> 7) & 15;
        int e = i & 127;
        int sa = s_order[bb * 16 + st];
        int sb = s_order[(2 + bb) * 16 + st];
        float dd = g_emb[(bb * 16 + sa) * 128 + e] - g_emb[((2 + bb) * 16 + sb) * 128 + e];
        acc += dd * dd;
    }
    #pragma unroll
    for (int off = 16; off; off >>= 1)
        acc += __shfl_down_sync(0xffffffffu, acc, off);
    if (lane == 0) s_nred[wid] = acc;
    __syncthreads();
    if (tid == 0) {
        float t2 = 0.f;
        for (int w = 0; w < 32; w++) t2 += s_nred[w];
        out[0] = t2 / 4096.f
               + 0.5f * (fabsf(g_norm[0] - g_norm[2]) + fabsf(g_norm[1] - g_norm[3]));
    }
}

// ---------------- launch ----------------------------------------------------
#define SMEM_STEPS (TT * 4 + AA * XSTR * 4)  // 65536 + 133120 = 198656

extern "C" void kernel_launch(void* const* d_in, const int* in_sizes, int n_in,
                              void* d_out, int out_size)
{
    (void)in_sizes; (void)n_in; (void)out_size;
    const float* a    = (const float*)d_in[0];
    const float* b    = (const float*)d_in[1];
    const float* d    = (const float*)d_in[2];
    const float* aemb = (const float*)d_in[3];
    const float* proj = (const float*)d_in[4];
    float* out = (float*)d_out;

    cudaFuncSetAttribute(steps_kernel,
                         cudaFuncAttributeMaxDynamicSharedMemorySize, SMEM_STEPS);

    prep_kernel<<<896, 128>>>(a, b, d);
    corr_kernel<<<512, 256>>>(1);     // xcorr -> g_xc4
    corr_kernel<<<1024, 256>>>(0);    // fm -> g_fm + g_cm
    steps_kernel<<<4, 1024, SMEM_STEPS>>>(aemb, proj, out);
}

// round 10
// speedup vs baseline: 1.5584x; 1.2539x over previous
#include <cuda_runtime.h>
#include <math.h>

#define TT    16384
#define AA    128
#define KK    128
#define NROW  4
#define NSTEP 16
#define EE    126
#define XSTR  260      // padded xc4 row stride in floats (multiple of 4)
#define CLUSTER 4      // CTAs per row; 32 atoms per CTA

// ---------------- device scratch (static: no allocations allowed) ----------
__device__ __align__(16) float    g_du[AA * KK];
__device__ __align__(16) float    g_xc4[AA * 4 * AA * XSTR]; // ~68MB
__device__ __align__(16) float    g_fm[NROW * AA * TT];
__device__ __align__(16) float    g_res[NROW * TT];
__device__ __align__(16) unsigned g_cm[NROW * TT];           // encoded colmax
__device__ __align__(16) float    g_emb[NROW * NSTEP * 128];
__device__ float                  g_norm[NROW];
__device__ int                    g_done;

// order-preserving float->uint encoding (monotone bijection)
__device__ __forceinline__ unsigned fenc(float f) {
    unsigned u = __float_as_uint(f);
    return (u & 0x80000000u) ? ~u : (u | 0x80000000u);
}

__device__ __forceinline__ unsigned smem_u32(const void* p) {
    return (unsigned)__cvta_generic_to_shared(p);
}
__device__ __forceinline__ unsigned mapa0(unsigned addr) {
    unsigned r;
    asm("mapa.shared::cluster.u32 %0, %1, %2;" : "=r"(r) : "r"(addr), "r"(0));
    return r;
}
__device__ __forceinline__ void st_remote_u32(unsigned addr, unsigned v) {
    asm volatile("st.shared::cluster.u32 [%0], %1;" :: "r"(addr), "r"(v) : "memory");
}
__device__ __forceinline__ unsigned ld_remote_u32(unsigned addr) {
    unsigned v;
    asm volatile("ld.shared::cluster.u32 %0, [%1];" : "=r"(v) : "r"(addr) : "memory");
    return v;
}
#define CLUSTER_SYNC() do { \
    asm volatile("barrier.cluster.arrive.aligned;" ::: "memory"); \
    asm volatile("barrier.cluster.wait.aligned;"   ::: "memory"); \
} while (0)

// ---------------- prep: d_unit + residual/cm init + xc4 edge zero ----------
__global__ void prep_kernel(const float* __restrict__ a,
                            const float* __restrict__ b,
                            const float* __restrict__ d)
{
    __shared__ float sred[4];
    int bx = blockIdx.x;
    int tid = threadIdx.x; // 128
    if (bx == 0 && tid == 0) g_done = 0;
    if (bx < AA) {
        float v = d[bx * KK + tid];
        float ss = v * v;
        #pragma unroll
        for (int off = 16; off; off >>= 1)
            ss += __shfl_down_sync(0xffffffffu, ss, off);
        if ((tid & 31) == 0) sred[tid >> 5] = ss;
        __syncthreads();
        float tot = sred[0] + sred[1] + sred[2] + sred[3];
        g_du[bx * KK + tid] = v / (sqrtf(tot) + 1e-8f);
    } else if (bx < 384) {
        int base = (bx - AA) * 256;
        #pragma unroll
        for (int j = tid; j < 256; j += 128) {
            int i = base + j;
            g_res[i] = (i < 2 * TT) ? a[i] : b[i - 2 * TT];
            g_cm[i] = 0u;
        }
    } else {
        // zero uncovered edges of g_xc4: for shift s, cols [0,s) and [256+s,260)
        int bb = bx - 384;           // 0..511
        int ai = bb >> 2, s = bb & 3;
        int aa2 = tid;
        #pragma unroll
        for (int idx = 0; idx < 4; idx++) {
            int jp = (idx < s) ? idx : 256 + idx;
            g_xc4[((ai * 4 + s) * AA + aa2) * XSTR + jp] = 0.f;
        }
    }
}

// ---------------- correlation kernel (round-3 inner loop), f32x2 -----------
__global__ __launch_bounds__(256) void corr_kernel(int mode)
{
    __shared__ float s_du[KK][64];
    __shared__ float s_sig[256];
    __shared__ float s_red[8][128];

    int blk = blockIdx.x;
    int tid = threadIdx.x;

    int row, tile, half;
    if (mode == 0) { half = blk & 1; row = (blk >> 1) & 3; tile = blk >> 3; }
    else           { half = blk & 1; tile = (blk >> 1) & 1; row = blk >> 2; }
    int t0 = tile * 128;

    for (int i = tid; i < 64 * KK; i += 256) {
        int al = i >> 7, k = i & 127;
        s_du[k][al] = g_du[(half * 64 + al) * KK + k];
    }

    const float* src;
    int srcLen, shift;
    if (mode == 0) { src = g_res + row * TT; srcLen = TT; shift = 64; }
    else           { src = g_du + row * KK;  srcLen = KK; shift = 127; }

    {
        int t = t0 + tid - shift;
        s_sig[tid] = (t >= 0 && t < srcLen) ? src[t] : 0.f;
    }
    __syncthreads();

    int x = tid & 31, y = tid >> 5;
    int c0 = x * 4, a0 = y * 8;

    unsigned long long acc2[4][4];
    #pragma unroll
    for (int j = 0; j < 4; j++)
        #pragma unroll
        for (int c = 0; c < 4; c++) acc2[j][c] = 0ull;

    unsigned r0 = __float_as_uint(s_sig[c0]);
    unsigned r1 = __float_as_uint(s_sig[c0 + 1]);
    unsigned r2 = __float_as_uint(s_sig[c0 + 2]);
    unsigned r3 = __float_as_uint(s_sig[c0 + 3]);

    #pragma unroll 4
    for (int k = 0; k < KK; k++) {
        unsigned long long dv[4];
        #pragma unroll
        for (int j = 0; j < 4; j++)
            dv[j] = *(const unsigned long long*)&s_du[k][a0 + 2 * j];

        unsigned long long rr0, rr1, rr2, rr3;
        asm("mov.b64 %0, {%1, %1};" : "=l"(rr0) : "r"(r0));
        asm("mov.b64 %0, {%1, %1};" : "=l"(rr1) : "r"(r1));
        asm("mov.b64 %0, {%1, %1};" : "=l"(rr2) : "r"(r2));
        asm("mov.b64 %0, {%1, %1};" : "=l"(rr3) : "r"(r3));

        #pragma unroll
        for (int j = 0; j < 4; j++) {
            asm("fma.rn.f32x2 %0, %1, %2, %0;" : "+l"(acc2[j][0]) : "l"(dv[j]), "l"(rr0));
            asm("fma.rn.f32x2 %0, %1, %2, %0;" : "+l"(acc2[j][1]) : "l"(dv[j]), "l"(rr1));
            asm("fma.rn.f32x2 %0, %1, %2, %0;" : "+l"(acc2[j][2]) : "l"(dv[j]), "l"(rr2));
            asm("fma.rn.f32x2 %0, %1, %2, %0;" : "+l"(acc2[j][3]) : "l"(dv[j]), "l"(rr3));
        }
        r0 = r1; r1 = r2; r2 = r3;
        r3 = __float_as_uint(s_sig[c0 + 4 + k]);
    }

    int a_base = half * 64 + a0;
    int t = t0 + c0;

    if (mode == 0) {
        float* out = g_fm + row * AA * TT;
        float cmax[4] = { -3.402823466e38f, -3.402823466e38f,
                          -3.402823466e38f, -3.402823466e38f };
        #pragma unroll
        for (int j = 0; j < 4; j++) {
            float lo[4], hi[4];
            #pragma unroll
            for (int c = 0; c < 4; c++) {
                lo[c] = __uint_as_float((unsigned)acc2[j][c]);
                hi[c] = __uint_as_float((unsigned)(acc2[j][c] >> 32));
                cmax[c] = fmaxf(cmax[c], fmaxf(lo[c], hi[c]));
            }
            *(float4*)(out + (a_base + 2 * j) * TT + t) =
                make_float4(lo[0], lo[1], lo[2], lo[3]);
            *(float4*)(out + (a_base + 2 * j + 1) * TT + t) =
                make_float4(hi[0], hi[1], hi[2], hi[3]);
        }
        #pragma unroll
        for (int c = 0; c < 4; c++) s_red[y][c0 + c] = cmax[c];
        __syncthreads();
        if (tid < 128) {
            float m = s_red[0][tid];
            #pragma unroll
            for (int w = 1; w < 8; w++) m = fmaxf(m, s_red[w][tid]);
            atomicMax(&g_cm[row * TT + t0 + tid], fenc(m));
        }
    } else {
        #pragma unroll
        for (int j = 0; j < 4; j++) {
            #pragma unroll
            for (int c = 0; c < 4; c++) {
                float lov = __uint_as_float((unsigned)acc2[j][c]);
                float hiv = __uint_as_float((unsigned)(acc2[j][c] >> 32));
                int jj = t + c;
                #pragma unroll
                for (int s = 0; s < 4; s++) {
                    long base = ((long)(row * 4 + s) * AA + a_base + 2 * j) * XSTR + jj + s;
                    g_xc4[base] = lov;
                    g_xc4[base + XSTR] = hiv;
                }
            }
        }
    }
}

// ---------------- steps: cluster of 4 CTAs per row -------------------------
// dynamic smem layout (identical across CTAs):
//   s_cm   [TT u32]        65536 B   (meaningful on rank 0 only)
//   s_tile [32*XSTR f]     33280 B   (per-rank local tile)
//   s_part [4*260 u32]      4160 B   (rank 0: partial colmax from each rank)
//   s_w    [260 u32]        1040 B   (per-rank local window colmax)
#define TILE_F     (32 * XSTR)
#define OFF_TILE   (TT * 4)
#define OFF_PART   (OFF_TILE + TILE_F * 4)
#define OFF_W      (OFF_PART + 4 * 260 * 4)
#define SMEM_STEPS (OFF_W + 260 * 4 + 16)

__global__ __launch_bounds__(1024, 1) __cluster_dims__(CLUSTER, 1, 1)
void steps_kernel(const float* __restrict__ atom_emb,
                  const float* __restrict__ proj,
                  float* __restrict__ out)
{
    extern __shared__ unsigned char smem_raw[];
    unsigned* s_cm   = (unsigned*)smem_raw;
    float*    s_tile = (float*)(smem_raw + OFF_TILE);
    unsigned* s_part = (unsigned*)(smem_raw + OFF_PART);
    unsigned* s_w    = (unsigned*)(smem_raw + OFF_W);

    __shared__ unsigned s_rk[32];
    __shared__ int      s_rt[32];
    __shared__ float    s_nred[32];
    __shared__ unsigned s_msg[4];     // [0]=v bits, [1]=ti, [2]=ai
    __shared__ int   sh_pa, sh_aa, sh_ti_prev;
    __shared__ int   s_last;
    __shared__ float s_keys[64];
    __shared__ int   s_order[64];
    __shared__ float s_proj[128];

    int r    = blockIdx.x >> 2;
    int rank = blockIdx.x & 3;
    int tid  = threadIdx.x;
    int lane = tid & 31, wid = tid >> 5;

    float* fmr  = g_fm  + r * AA * TT;
    float* resr = g_res + r * TT;

    // rank 0: load initial colmax into smem
    if (rank == 0) {
        #pragma unroll
        for (int q = 0; q < 4; q++)
            ((uint4*)s_cm)[tid + 1024 * q] =
                ((const uint4*)(g_cm + r * TT))[tid + 1024 * q];
        __syncthreads();
    }

    for (int step = 0; step < NSTEP; step++) {
        CLUSTER_SYNC();   // A: previous step's DSMEM partials + gmem fm visible

        if (rank == 0) {
            // combine previous window partials into s_cm
            if (step > 0 && tid < 260) {
                int w0p = (sh_ti_prev - 127) & ~3;
                int t = w0p + tid;
                if (t >= 0 && t < TT) {
                    unsigned m = s_part[tid];
                    unsigned m1 = s_part[260 + tid];  if (m1 > m) m = m1;
                    unsigned m2 = s_part[520 + tid];  if (m2 > m) m = m2;
                    unsigned m3 = s_part[780 + tid];  if (m3 > m) m = m3;
                    s_cm[t] = m;
                }
            }
            __syncthreads();

            // phase 1: global argmax over s_cm (tie -> lowest t)
            unsigned bk = 0u;
            int bt = 0x7fffffff;
            #pragma unroll
            for (int q = 0; q < 4; q++) {
                uint4 u = ((const uint4*)s_cm)[tid + 1024 * q];
                int tb = (tid + 1024 * q) * 4;
                if (u.x > bk) { bk = u.x; bt = tb; }
                if (u.y > bk) { bk = u.y; bt = tb + 1; }
                if (u.z > bk) { bk = u.z; bt = tb + 2; }
                if (u.w > bk) { bk = u.w; bt = tb + 3; }
            }
            #pragma unroll
            for (int off = 16; off; off >>= 1) {
                unsigned ok = __shfl_down_sync(0xffffffffu, bk, off);
                int      ot = __shfl_down_sync(0xffffffffu, bt, off);
                if (ok > bk || (ok == bk && ot < bt)) { bk = ok; bt = ot; }
            }
            if (lane == 0) { s_rk[wid] = bk; s_rt[wid] = bt; }
            __syncthreads();

            // phase 2: warp 0 final reduce + atom argmax at winning column
            if (wid == 0) {
                bk = s_rk[lane]; bt = s_rt[lane];
                #pragma unroll
                for (int off = 16; off; off >>= 1) {
                    unsigned ok = __shfl_down_sync(0xffffffffu, bk, off);
                    int      ot = __shfl_down_sync(0xffffffffu, bt, off);
                    if (ok > bk || (ok == bk && ot < bt)) { bk = ok; bt = ot; }
                }
                bt = __shfl_sync(0xffffffffu, bt, 0);

                float av = -3.402823466e38f;
                int aarg = 0x7fffffff;
                #pragma unroll
                for (int a = lane; a < AA; a += 32) {
                    float fv = __ldcg(&fmr[a * TT + bt]);   // L2, never stale L1
                    if (fv > av) { av = fv; aarg = a; }
                }
                #pragma unroll
                for (int off = 16; off; off >>= 1) {
                    float ov = __shfl_down_sync(0xffffffffu, av, off);
                    int   oa = __shfl_down_sync(0xffffffffu, aarg, off);
                    if (ov > av || (ov == av && oa < aarg)) { av = ov; aarg = oa; }
                }
                if (lane == 0) {
                    s_msg[0] = __float_as_uint(av);
                    s_msg[1] = (unsigned)bt;
                    s_msg[2] = (unsigned)aarg;
                    sh_ti_prev = bt;
                    int pa, aa2;
                    if (av > 0.f)      { pa = bt; aa2 = aarg; }
                    else if (av < 0.f) { pa = (bt == 0) ? 1 : 0; aa2 = (aarg == 0) ? 1 : 0; }
                    else               { pa = 0; aa2 = 0; }
                    sh_pa = pa; sh_aa = aa2;
                }
            }
            __syncthreads();
        }

        CLUSTER_SYNC();   // B: rank0's s_msg visible cluster-wide

        if (rank != 0 && tid < 3)
            s_msg[tid] = ld_remote_u32(mapa0(smem_u32(&s_msg[tid])));
        if (tid < 260) s_w[tid] = 0u;
        __syncthreads();

        float v = __uint_as_float(s_msg[0]);
        int ti = (int)s_msg[1], ai = (int)s_msg[2];
        int w0  = (ti - 127) & ~3;
        int shf = (ti - 127) - w0;

        // rank 0: embedding + residual update
        if (rank == 0) {
            if (tid < 128) {
                float e;
                if (tid == 0)      e = (float)sh_pa * (20.f / (float)(TT - 1));
                else if (tid == 1) e = v;
                else               e = atom_emb[sh_aa * EE + (tid - 2)];
                g_emb[(r * NSTEP + step) * 128 + tid] = e;
            } else if (tid < 256) {
                int k = tid - 128;
                int t = ti - 64 + k;
                if (t >= 0 && t < TT) resr[t] -= v * g_du[ai * KK + k];
            }
        }

        // phase 3b: warp wid updates atom (rank*32 + wid); fm gmem + local tile
        {
            int a = rank * 32 + wid;
            float*       fp = fmr + a * TT;
            const float* xp = g_xc4 + ((long)(ai * 4 + shf) * AA + a) * XSTR;
            float*       tp = s_tile + wid * XSTR;
            #pragma unroll
            for (int it = 0; it < 3; it++) {
                int jj4 = lane + 32 * it;
                if (jj4 < 65) {
                    int jp = jj4 * 4;
                    int t = w0 + jp;
                    if (t >= 0 && t + 3 < TT) {
                        float4 f = *(const float4*)(fp + t);
                        float4 xx = *(const float4*)(xp + jp);
                        f.x -= v * xx.x; f.y -= v * xx.y;
                        f.z -= v * xx.z; f.w -= v * xx.w;
                        *(float4*)(fp + t) = f;
                        *(float4*)(tp + jp) = f;
                    } else {
                        #pragma unroll
                        for (int e = 0; e < 4; e++) {
                            int te = t + e;
                            if (te >= 0 && te < TT) {
                                float f = fp[te] - v * xp[jp + e];
                                fp[te] = f;
                                tp[jp + e] = f;
                            }
                        }
                    }
                }
            }
        }
        __syncthreads();

        // phase 4: local colmax partial over 32 atoms -> s_w (u32 atomicMax)
        {
            int c4 = tid & 63, sub = tid >> 6;      // 16 subs x 2 atoms
            #pragma unroll
            for (int pass = 0; pass < 2; pass++) {
                int cc4, ss;
                if (pass == 0) { cc4 = c4; ss = sub; }
                else { if (tid >= 16) break; cc4 = 64; ss = tid; }
                float m0 = -3.402823466e38f, m1 = m0, m2 = m0, m3 = m0;
                #pragma unroll
                for (int i = 0; i < 2; i++) {
                    int a = ss * 2 + i;
                    float4 xx = *(const float4*)(s_tile + a * XSTR + 4 * cc4);
                    m0 = fmaxf(m0, xx.x); m1 = fmaxf(m1, xx.y);
                    m2 = fmaxf(m2, xx.z); m3 = fmaxf(m3, xx.w);
                }
                int cb = 4 * cc4;
                atomicMax(&s_w[cb],     fenc(m0));
                atomicMax(&s_w[cb + 1], fenc(m1));
                atomicMax(&s_w[cb + 2], fenc(m2));
                atomicMax(&s_w[cb + 3], fenc(m3));
            }
        }
        __syncthreads();

        // export partials to rank 0
        if (tid < 260) {
            if (rank == 0) s_part[tid] = s_w[tid];
            else st_remote_u32(mapa0(smem_u32(&s_part[rank * 260 + tid])), s_w[tid]);
        }
        // loop back: CLUSTER_SYNC A publishes these
    }

    CLUSTER_SYNC();   // final: all DSMEM traffic complete; safe to diverge
    if (rank != 0) return;

    // --- residual norm (rank 0) ---
    float ss = 0.f;
    #pragma unroll
    for (int q = 0; q < 4; q++) {
        float4 vv = ((const float4*)resr)[tid + 1024 * q];
        ss += vv.x * vv.x + vv.y * vv.y + vv.z * vv.z + vv.w * vv.w;
    }
    #pragma unroll
    for (int off = 16; off; off >>= 1)
        ss += __shfl_down_sync(0xffffffffu, ss, off);
    if (lane == 0) s_nred[wid] = ss;
    __syncthreads();
    if (wid == 0) {
        float t2 = s_nred[lane];
        #pragma unroll
        for (int off = 16; off; off >>= 1)
            t2 += __shfl_down_sync(0xffffffffu, t2, off);
        if (lane == 0) g_norm[r] = sqrtf(t2);
    }

    // --- fused final loss: last rank-0 to finish computes it ---
    __threadfence();
    __syncthreads();
    if (tid == 0) s_last = (atomicAdd(&g_done, 1) == NROW - 1);
    __syncthreads();
    if (!s_last) return;
    __threadfence();

    if (tid < 128) s_proj[tid] = proj[tid];
    __syncthreads();

    {
        int key = wid * 2 + (lane >> 4);
        int sl = lane & 15;
        const float* e = g_emb + key * 128;
        float p = 0.f;
        #pragma unroll
        for (int q = 0; q < 8; q++) {
            int j = sl + 16 * q;
            p += e[j] * s_proj[j];
        }
        #pragma unroll
        for (int off = 1; off < 16; off <<= 1)
            p += __shfl_xor_sync(0xffffffffu, p, off);
        if (sl == 0) s_keys[key] = p;
    }
    __syncthreads();

    if (tid < 4) {   // stable insertion sort, ascending (matches jnp.argsort)
        int ord[16];
        for (int i = 0; i < 16; i++) ord[i] = i;
        for (int i = 1; i < 16; i++) {
            int oi = ord[i];
            float ki = s_keys[tid * 16 + oi];
            int j = i - 1;
            while (j >= 0 && s_keys[tid * 16 + ord[j]] > ki) { ord[j + 1] = ord[j]; j--; }
            ord[j + 1] = oi;
        }
        for (int i = 0; i < 16; i++) s_order[tid * 16 + i] = ord[i];
    }
    __syncthreads();

    float acc = 0.f;
    #pragma unroll
    for (int q = 0; q < 4; q++) {
        int i = tid + 1024 * q;
        int bb = i >> 11;
        int st = (i >> 7) & 15;
        int e = i & 127;
        int sa = s_order[bb * 16 + st];
        int sb = s_order[(2 + bb) * 16 + st];
        float dd = g_emb[(bb * 16 + sa) * 128 + e] - g_emb[((2 + bb) * 16 + sb) * 128 + e];
        acc += dd * dd;
    }
    #pragma unroll
    for (int off = 16; off; off >>= 1)
        acc += __shfl_down_sync(0xffffffffu, acc, off);
    if (lane == 0) s_nred[wid] = acc;
    __syncthreads();
    if (tid == 0) {
        float t2 = 0.f;
        for (int w = 0; w < 32; w++) t2 += s_nred[w];
        out[0] = t2 / 4096.f
               + 0.5f * (fabsf(g_norm[0] - g_norm[2]) + fabsf(g_norm[1] - g_norm[3]));
    }
}

// ---------------- launch ----------------------------------------------------
extern "C" void kernel_launch(void* const* d_in, const int* in_sizes, int n_in,
                              void* d_out, int out_size)
{
    (void)in_sizes; (void)n_in; (void)out_size;
    const float* a    = (const float*)d_in[0];
    const float* b    = (const float*)d_in[1];
    const float* d    = (const float*)d_in[2];
    const float* aemb = (const float*)d_in[3];
    const float* proj = (const float*)d_in[4];
    float* out = (float*)d_out;

    cudaFuncSetAttribute(steps_kernel,
                         cudaFuncAttributeMaxDynamicSharedMemorySize, SMEM_STEPS);

    prep_kernel<<<896, 128>>>(a, b, d);
    corr_kernel<<<512, 256>>>(1);     // xcorr -> g_xc4
    corr_kernel<<<1024, 256>>>(0);    // fm -> g_fm + g_cm
    steps_kernel<<<NROW * CLUSTER, 1024, SMEM_STEPS>>>(aemb, proj, out);
}

// round 11
// speedup vs baseline: 1.7472x; 1.1212x over previous
#include <cuda_runtime.h>
#include <math.h>

#define TT    16384
#define AA    128
#define KK    128
#define NROW  4
#define NSTEP 16
#define EE    126
#define XSTR  260      // padded xc4 row stride in floats (multiple of 4)
#define CLUSTER 4      // CTAs per row; 32 atoms per CTA

// ---------------- device scratch (static: no allocations allowed) ----------
__device__ __align__(16) float    g_du[AA * KK];
__device__ __align__(16) float    g_xc4[AA * 4 * AA * XSTR]; // ~68MB
__device__ __align__(16) float    g_fm[NROW * AA * TT];
__device__ __align__(16) float    g_res[NROW * TT];
__device__ __align__(16) unsigned g_cm[NROW * TT];           // encoded colmax
__device__ __align__(16) float    g_emb[NROW * NSTEP * 128];
__device__ float                  g_norm[NROW];
__device__ int                    g_done;

// order-preserving float->uint encoding (monotone bijection)
__device__ __forceinline__ unsigned fenc(float f) {
    unsigned u = __float_as_uint(f);
    return (u & 0x80000000u) ? ~u : (u | 0x80000000u);
}

__device__ __forceinline__ unsigned smem_u32(const void* p) {
    return (unsigned)__cvta_generic_to_shared(p);
}
__device__ __forceinline__ unsigned mapa_rank(unsigned addr, int r) {
    unsigned out;
    asm("mapa.shared::cluster.u32 %0, %1, %2;" : "=r"(out) : "r"(addr), "r"(r));
    return out;
}
__device__ __forceinline__ void st_remote_u32(unsigned addr, unsigned v) {
    asm volatile("st.shared::cluster.u32 [%0], %1;" :: "r"(addr), "r"(v) : "memory");
}
#define CLUSTER_SYNC() do { \
    asm volatile("barrier.cluster.arrive.aligned;" ::: "memory"); \
    asm volatile("barrier.cluster.wait.aligned;"   ::: "memory"); \
} while (0)

// ---------------- prep: d_unit + residual/cm init + xc4 edge zero ----------
__global__ void prep_kernel(const float* __restrict__ a,
                            const float* __restrict__ b,
                            const float* __restrict__ d)
{
    __shared__ float sred[4];
    int bx = blockIdx.x;
    int tid = threadIdx.x; // 128
    if (bx == 0 && tid == 0) g_done = 0;
    if (bx < AA) {
        float v = d[bx * KK + tid];
        float ss = v * v;
        #pragma unroll
        for (int off = 16; off; off >>= 1)
            ss += __shfl_down_sync(0xffffffffu, ss, off);
        if ((tid & 31) == 0) sred[tid >> 5] = ss;
        __syncthreads();
        float tot = sred[0] + sred[1] + sred[2] + sred[3];
        g_du[bx * KK + tid] = v / (sqrtf(tot) + 1e-8f);
    } else if (bx < 384) {
        int base = (bx - AA) * 256;
        #pragma unroll
        for (int j = tid; j < 256; j += 128) {
            int i = base + j;
            g_res[i] = (i < 2 * TT) ? a[i] : b[i - 2 * TT];
            g_cm[i] = 0u;
        }
    } else {
        // zero uncovered edges of g_xc4: for shift s, cols [0,s) and [256+s,260)
        int bb = bx - 384;           // 0..511
        int ai = bb >> 2, s = bb & 3;
        int aa2 = tid;
        #pragma unroll
        for (int idx = 0; idx < 4; idx++) {
            int jp = (idx < s) ? idx : 256 + idx;
            g_xc4[((ai * 4 + s) * AA + aa2) * XSTR + jp] = 0.f;
        }
    }
}

// ---------------- correlation kernel, f32x2 --------------------------------
// mode 0: fm    (1024 blocks) -> g_fm + colmax
// mode 1: xcorr (512 blocks)  -> g_xc4 via smem staging + coalesced stores
__global__ __launch_bounds__(256) void corr_kernel(int mode)
{
    __shared__ float s_du[KK][64];   // 32KB; reused as 64x128 stage in mode 1
    __shared__ float s_sig[256];
    __shared__ float s_red[8][128];

    int blk = blockIdx.x;
    int tid = threadIdx.x;

    int row, tile, half;
    if (mode == 0) { half = blk & 1; row = (blk >> 1) & 3; tile = blk >> 3; }
    else           { half = blk & 1; tile = (blk >> 1) & 1; row = blk >> 2; }
    int t0 = tile * 128;

    for (int i = tid; i < 64 * KK; i += 256) {
        int al = i >> 7, k = i & 127;
        s_du[k][al] = g_du[(half * 64 + al) * KK + k];
    }

    const float* src;
    int srcLen, shift;
    if (mode == 0) { src = g_res + row * TT; srcLen = TT; shift = 64; }
    else           { src = g_du + row * KK;  srcLen = KK; shift = 127; }

    {
        int t = t0 + tid - shift;
        s_sig[tid] = (t >= 0 && t < srcLen) ? src[t] : 0.f;
    }
    __syncthreads();

    int x = tid & 31, y = tid >> 5;
    int c0 = x * 4, a0 = y * 8;

    unsigned long long acc2[4][4];
    #pragma unroll
    for (int j = 0; j < 4; j++)
        #pragma unroll
        for (int c = 0; c < 4; c++) acc2[j][c] = 0ull;

    unsigned r0 = __float_as_uint(s_sig[c0]);
    unsigned r1 = __float_as_uint(s_sig[c0 + 1]);
    unsigned r2 = __float_as_uint(s_sig[c0 + 2]);
    unsigned r3 = __float_as_uint(s_sig[c0 + 3]);

    #pragma unroll 4
    for (int k = 0; k < KK; k++) {
        unsigned long long dv[4];
        #pragma unroll
        for (int j = 0; j < 4; j++)
            dv[j] = *(const unsigned long long*)&s_du[k][a0 + 2 * j];

        unsigned long long rr0, rr1, rr2, rr3;
        asm("mov.b64 %0, {%1, %1};" : "=l"(rr0) : "r"(r0));
        asm("mov.b64 %0, {%1, %1};" : "=l"(rr1) : "r"(r1));
        asm("mov.b64 %0, {%1, %1};" : "=l"(rr2) : "r"(r2));
        asm("mov.b64 %0, {%1, %1};" : "=l"(rr3) : "r"(r3));

        #pragma unroll
        for (int j = 0; j < 4; j++) {
            asm("fma.rn.f32x2 %0, %1, %2, %0;" : "+l"(acc2[j][0]) : "l"(dv[j]), "l"(rr0));
            asm("fma.rn.f32x2 %0, %1, %2, %0;" : "+l"(acc2[j][1]) : "l"(dv[j]), "l"(rr1));
            asm("fma.rn.f32x2 %0, %1, %2, %0;" : "+l"(acc2[j][2]) : "l"(dv[j]), "l"(rr2));
            asm("fma.rn.f32x2 %0, %1, %2, %0;" : "+l"(acc2[j][3]) : "l"(dv[j]), "l"(rr3));
        }
        r0 = r1; r1 = r2; r2 = r3;
        r3 = __float_as_uint(s_sig[c0 + 4 + k]);
    }

    int a_base = half * 64 + a0;
    int t = t0 + c0;

    if (mode == 0) {
        float* out = g_fm + row * AA * TT;
        float cmax[4] = { -3.402823466e38f, -3.402823466e38f,
                          -3.402823466e38f, -3.402823466e38f };
        #pragma unroll
        for (int j = 0; j < 4; j++) {
            float lo[4], hi[4];
            #pragma unroll
            for (int c = 0; c < 4; c++) {
                lo[c] = __uint_as_float((unsigned)acc2[j][c]);
                hi[c] = __uint_as_float((unsigned)(acc2[j][c] >> 32));
                cmax[c] = fmaxf(cmax[c], fmaxf(lo[c], hi[c]));
            }
            *(float4*)(out + (a_base + 2 * j) * TT + t) =
                make_float4(lo[0], lo[1], lo[2], lo[3]);
            *(float4*)(out + (a_base + 2 * j + 1) * TT + t) =
                make_float4(hi[0], hi[1], hi[2], hi[3]);
        }
        #pragma unroll
        for (int c = 0; c < 4; c++) s_red[y][c0 + c] = cmax[c];
        __syncthreads();
        if (tid < 128) {
            float m = s_red[0][tid];
            #pragma unroll
            for (int w = 1; w < 8; w++) m = fmaxf(m, s_red[w][tid]);
            atomicMax(&g_cm[row * TT + t0 + tid], fenc(m));
        }
    } else {
        // stage 64x128 tile into s_du's storage, then coalesced shifted copies
        float* s_stage = &s_du[0][0];     // [a_local][c] : a*128 + c
        __syncthreads();                  // k-loop reads of s_du complete
        #pragma unroll
        for (int j = 0; j < 4; j++) {
            float lo[4], hi[4];
            #pragma unroll
            for (int c = 0; c < 4; c++) {
                lo[c] = __uint_as_float((unsigned)acc2[j][c]);
                hi[c] = __uint_as_float((unsigned)(acc2[j][c] >> 32));
            }
            *(float4*)(s_stage + (a0 + 2 * j) * 128 + c0) =
                make_float4(lo[0], lo[1], lo[2], lo[3]);
            *(float4*)(s_stage + (a0 + 2 * j + 1) * 128 + c0) =
                make_float4(hi[0], hi[1], hi[2], hi[3]);
        }
        __syncthreads();

        #pragma unroll
        for (int s = 0; s < 4; s++) {
            int nF4 = (s == 0) ? 32 : 31;
            for (int i = tid; i < 64 * nF4; i += 256) {
                int a = i / nF4, mi = i - a * nF4;
                int localc = (s == 0) ? (4 * mi) : (4 + 4 * mi - s);
                int dstf4  = (s == 0) ? (t0 / 4 + mi) : (t0 / 4 + 1 + mi);
                const float* sp = s_stage + a * 128 + localc;
                float4 v = make_float4(sp[0], sp[1], sp[2], sp[3]);
                long base = ((long)(row * 4 + s) * AA + half * 64 + a) * XSTR;
                *(float4*)(g_xc4 + base + 4 * dstf4) = v;
            }
            if (s > 0) {
                for (int i = tid; i < 64 * 4; i += 256) {
                    int a = i >> 2, q = i & 3;
                    long base = ((long)(row * 4 + s) * AA + half * 64 + a) * XSTR;
                    if (q < 4 - s) {
                        g_xc4[base + t0 + s + q] = s_stage[a * 128 + q];
                    } else {
                        int qq = q - (4 - s);          // 0..s-1
                        g_xc4[base + t0 + 128 + qq] = s_stage[a * 128 + 128 - s + qq];
                    }
                }
            }
        }
    }
}

// ---------------- steps: cluster of 4 CTAs per row, replicated s_cm --------
// dynamic smem per CTA:
//   s_cm   [TT u32]          65536 B  (full colmax, replicated in every rank)
//   s_tile [32*XSTR f]       33280 B  (per-rank local tile)
//   s_part [2][4][260] u32    8320 B  (double-buffered all-to-all partials)
//   s_w    [260 u32]          1040 B  (per-rank local window partial)
#define OFF_TILE   (TT * 4)
#define OFF_PART   (OFF_TILE + 32 * XSTR * 4)
#define OFF_W      (OFF_PART + 2 * 4 * 260 * 4)
#define SMEM_STEPS (OFF_W + 260 * 4 + 16)

__global__ __launch_bounds__(1024, 1) __cluster_dims__(CLUSTER, 1, 1)
void steps_kernel(const float* __restrict__ atom_emb,
                  const float* __restrict__ proj,
                  float* __restrict__ out)
{
    extern __shared__ unsigned char smem_raw[];
    unsigned* s_cm   = (unsigned*)smem_raw;
    float*    s_tile = (float*)(smem_raw + OFF_TILE);
    unsigned* s_part = (unsigned*)(smem_raw + OFF_PART);   // [buf][src][260]
    unsigned* s_w    = (unsigned*)(smem_raw + OFF_W);

    __shared__ unsigned s_rk[32];
    __shared__ int      s_rt[32];
    __shared__ float    s_nred[32];
    __shared__ float sh_v;
    __shared__ int   sh_ti, sh_ai, sh_pa, sh_aa;
    __shared__ int   s_last;
    __shared__ float s_keys[64];
    __shared__ int   s_order[64];
    __shared__ float s_proj[128];

    int r    = blockIdx.x >> 2;
    int rank = blockIdx.x & 3;
    int tid  = threadIdx.x;
    int lane = tid & 31, wid = tid >> 5;

    float* fmr  = g_fm  + r * AA * TT;
    float* resr = g_res + r * TT;

    // every rank loads the full initial colmax
    #pragma unroll
    for (int q = 0; q < 4; q++)
        ((uint4*)s_cm)[tid + 1024 * q] =
            ((const uint4*)(g_cm + r * TT))[tid + 1024 * q];
    __syncthreads();

    int prev_w0 = 0;

    for (int step = 0; step < NSTEP; step++) {
        CLUSTER_SYNC();   // prev-step partial exports + gmem fm writes visible

        // combine previous window partials into replicated s_cm (all ranks)
        if (step > 0 && tid < 260) {
            int pb = (step - 1) & 1;
            int t = prev_w0 + tid;
            if (t >= 0 && t < TT) {
                unsigned m  = s_part[(pb * 4 + 0) * 260 + tid];
                unsigned m1 = s_part[(pb * 4 + 1) * 260 + tid]; if (m1 > m) m = m1;
                unsigned m2 = s_part[(pb * 4 + 2) * 260 + tid]; if (m2 > m) m = m2;
                unsigned m3 = s_part[(pb * 4 + 3) * 260 + tid]; if (m3 > m) m = m3;
                s_cm[t] = m;
            }
        }
        __syncthreads();

        // phase 1: full argmax over s_cm -- REPLICATED on every rank
        {
            unsigned bk = 0u;
            int bt = 0x7fffffff;
            #pragma unroll
            for (int q = 0; q < 4; q++) {
                uint4 u = ((const uint4*)s_cm)[tid + 1024 * q];
                int tb = (tid + 1024 * q) * 4;
                if (u.x > bk) { bk = u.x; bt = tb; }
                if (u.y > bk) { bk = u.y; bt = tb + 1; }
                if (u.z > bk) { bk = u.z; bt = tb + 2; }
                if (u.w > bk) { bk = u.w; bt = tb + 3; }
            }
            #pragma unroll
            for (int off = 16; off; off >>= 1) {
                unsigned ok = __shfl_down_sync(0xffffffffu, bk, off);
                int      ot = __shfl_down_sync(0xffffffffu, bt, off);
                if (ok > bk || (ok == bk && ot < bt)) { bk = ok; bt = ot; }
            }
            if (lane == 0) { s_rk[wid] = bk; s_rt[wid] = bt; }
        }
        __syncthreads();

        if (wid == 0) {
            unsigned bk = s_rk[lane];
            int bt = s_rt[lane];
            #pragma unroll
            for (int off = 16; off; off >>= 1) {
                unsigned ok = __shfl_down_sync(0xffffffffu, bk, off);
                int      ot = __shfl_down_sync(0xffffffffu, bt, off);
                if (ok > bk || (ok == bk && ot < bt)) { bk = ok; bt = ot; }
            }
            bt = __shfl_sync(0xffffffffu, bt, 0);

            float av = -3.402823466e38f;
            int aarg = 0x7fffffff;
            #pragma unroll
            for (int a = lane; a < AA; a += 32) {
                float fv = __ldcg(&fmr[a * TT + bt]);   // L2, never stale L1
                if (fv > av) { av = fv; aarg = a; }
            }
            #pragma unroll
            for (int off = 16; off; off >>= 1) {
                float ov = __shfl_down_sync(0xffffffffu, av, off);
                int   oa = __shfl_down_sync(0xffffffffu, aarg, off);
                if (ov > av || (ov == av && oa < aarg)) { av = ov; aarg = oa; }
            }
            if (lane == 0) {
                sh_v = av; sh_ti = bt; sh_ai = aarg;
                int pa, aa2;
                if (av > 0.f)      { pa = bt; aa2 = aarg; }
                else if (av < 0.f) { pa = (bt == 0) ? 1 : 0; aa2 = (aarg == 0) ? 1 : 0; }
                else               { pa = 0; aa2 = 0; }
                sh_pa = pa; sh_aa = aa2;
            }
        }
        __syncthreads();

        float v = sh_v;
        int ti = sh_ti, ai = sh_ai;
        int w0  = (ti - 127) & ~3;
        int shf = (ti - 127) - w0;

        // rank 0: embedding + residual; others' low threads zero s_w
        if (rank == 0 && tid < 128) {
            float e;
            if (tid == 0)      e = (float)sh_pa * (20.f / (float)(TT - 1));
            else if (tid == 1) e = v;
            else               e = atom_emb[sh_aa * EE + (tid - 2)];
            g_emb[(r * NSTEP + step) * 128 + tid] = e;
        } else if (rank == 0 && tid < 256) {
            int k = tid - 128;
            int t = ti - 64 + k;
            if (t >= 0 && t < TT) resr[t] -= v * g_du[ai * KK + k];
        }
        if (tid >= 256 && tid < 516) s_w[tid - 256] = 0u;

        // phase 3b: warp wid updates atom (rank*32 + wid)
        {
            int a = rank * 32 + wid;
            float*       fp = fmr + a * TT;
            const float* xp = g_xc4 + ((long)(ai * 4 + shf) * AA + a) * XSTR;
            float*       tp = s_tile + wid * XSTR;
            #pragma unroll
            for (int it = 0; it < 3; it++) {
                int jj4 = lane + 32 * it;
                if (jj4 < 65) {
                    int jp = jj4 * 4;
                    int t = w0 + jp;
                    if (t >= 0 && t + 3 < TT) {
                        float4 f = *(const float4*)(fp + t);
                        float4 xx = *(const float4*)(xp + jp);
                        f.x -= v * xx.x; f.y -= v * xx.y;
                        f.z -= v * xx.z; f.w -= v * xx.w;
                        *(float4*)(fp + t) = f;
                        *(float4*)(tp + jp) = f;
                    } else {
                        #pragma unroll
                        for (int e = 0; e < 4; e++) {
                            int te = t + e;
                            if (te >= 0 && te < TT) {
                                float f = fp[te] - v * xp[jp + e];
                                fp[te] = f;
                                tp[jp + e] = f;
                            }
                        }
                    }
                }
            }
        }
        __syncthreads();

        // phase 4: local colmax partial over this rank's 32 atoms -> s_w
        {
            int c4 = tid & 63, sub = tid >> 6;      // 16 subs x 2 atoms
            #pragma unroll
            for (int pass = 0; pass < 2; pass++) {
                int cc4, ss;
                if (pass == 0) { cc4 = c4; ss = sub; }
                else { if (tid >= 16) break; cc4 = 64; ss = tid; }
                float m0 = -3.402823466e38f, m1 = m0, m2 = m0, m3 = m0;
                #pragma unroll
                for (int i = 0; i < 2; i++) {
                    int a = ss * 2 + i;
                    float4 xx = *(const float4*)(s_tile + a * XSTR + 4 * cc4);
                    m0 = fmaxf(m0, xx.x); m1 = fmaxf(m1, xx.y);
                    m2 = fmaxf(m2, xx.z); m3 = fmaxf(m3, xx.w);
                }
                int cb = 4 * cc4;
                atomicMax(&s_w[cb],     fenc(m0));
                atomicMax(&s_w[cb + 1], fenc(m1));
                atomicMax(&s_w[cb + 2], fenc(m2));
                atomicMax(&s_w[cb + 3], fenc(m3));
            }
        }
        __syncthreads();

        // export this rank's partial to ALL ranks' s_part[step&1][rank]
        if (tid < 260) {
            unsigned val = s_w[tid];
            int buf = step & 1;
            unsigned loc = smem_u32(&s_part[(buf * 4 + rank) * 260 + tid]);
            s_part[(buf * 4 + rank) * 260 + tid] = val;      // own copy
            #pragma unroll
            for (int d = 0; d < 4; d++)
                if (d != rank) st_remote_u32(mapa_rank(loc, d), val);
        }

        prev_w0 = w0;
    }

    CLUSTER_SYNC();   // all DSMEM traffic complete; safe to diverge
    if (rank != 0) return;

    // --- residual norm (rank 0) ---
    float ss = 0.f;
    #pragma unroll
    for (int q = 0; q < 4; q++) {
        float4 vv = ((const float4*)resr)[tid + 1024 * q];
        ss += vv.x * vv.x + vv.y * vv.y + vv.z * vv.z + vv.w * vv.w;
    }
    #pragma unroll
    for (int off = 16; off; off >>= 1)
        ss += __shfl_down_sync(0xffffffffu, ss, off);
    if (lane == 0) s_nred[wid] = ss;
    __syncthreads();
    if (wid == 0) {
        float t2 = s_nred[lane];
        #pragma unroll
        for (int off = 16; off; off >>= 1)
            t2 += __shfl_down_sync(0xffffffffu, t2, off);
        if (lane == 0) g_norm[r] = sqrtf(t2);
    }

    // --- fused final loss: last rank-0 to finish computes it ---
    __threadfence();
    __syncthreads();
    if (tid == 0) s_last = (atomicAdd(&g_done, 1) == NROW - 1);
    __syncthreads();
    if (!s_last) return;
    __threadfence();

    if (tid < 128) s_proj[tid] = proj[tid];
    __syncthreads();

    {
        int key = wid * 2 + (lane >> 4);
        int sl = lane & 15;
        const float* e = g_emb + key * 128;
        float p = 0.f;
        #pragma unroll
        for (int q = 0; q < 8; q++) {
            int j = sl + 16 * q;
            p += e[j] * s_proj[j];
        }
        #pragma unroll
        for (int off = 1; off < 16; off <<= 1)
            p += __shfl_xor_sync(0xffffffffu, p, off);
        if (sl == 0) s_keys[key] = p;
    }
    __syncthreads();

    if (tid < 4) {   // stable insertion sort, ascending (matches jnp.argsort)
        int ord[16];
        for (int i = 0; i < 16; i++) ord[i] = i;
        for (int i = 1; i < 16; i++) {
            int oi = ord[i];
            float ki = s_keys[tid * 16 + oi];
            int j = i - 1;
            while (j >= 0 && s_keys[tid * 16 + ord[j]] > ki) { ord[j + 1] = ord[j]; j--; }
            ord[j + 1] = oi;
        }
        for (int i = 0; i < 16; i++) s_order[tid * 16 + i] = ord[i];
    }
    __syncthreads();

    float acc = 0.f;
    #pragma unroll
    for (int q = 0; q < 4; q++) {
        int i = tid + 1024 * q;
        int bb = i >> 11;
        int st = (i >> 7) & 15;
        int e = i & 127;
        int sa = s_order[bb * 16 + st];
        int sb = s_order[(2 + bb) * 16 + st];
        float dd = g_emb[(bb * 16 + sa) * 128 + e] - g_emb[((2 + bb) * 16 + sb) * 128 + e];
        acc += dd * dd;
    }
    #pragma unroll
    for (int off = 16; off; off >>= 1)
        acc += __shfl_down_sync(0xffffffffu, acc, off);
    if (lane == 0) s_nred[wid] = acc;
    __syncthreads();
    if (tid == 0) {
        float t2 = 0.f;
        for (int w = 0; w < 32; w++) t2 += s_nred[w];
        out[0] = t2 / 4096.f
               + 0.5f * (fabsf(g_norm[0] - g_norm[2]) + fabsf(g_norm[1] - g_norm[3]));
    }
}

// ---------------- launch ----------------------------------------------------
extern "C" void kernel_launch(void* const* d_in, const int* in_sizes, int n_in,
                              void* d_out, int out_size)
{
    (void)in_sizes; (void)n_in; (void)out_size;
    const float* a    = (const float*)d_in[0];
    const float* b    = (const float*)d_in[1];
    const float* d    = (const float*)d_in[2];
    const float* aemb = (const float*)d_in[3];
    const float* proj = (const float*)d_in[4];
    float* out = (float*)d_out;

    cudaFuncSetAttribute(steps_kernel,
                         cudaFuncAttributeMaxDynamicSharedMemorySize, SMEM_STEPS);

    prep_kernel<<<896, 128>>>(a, b, d);
    corr_kernel<<<512, 256>>>(1);     // xcorr -> g_xc4 (staged, coalesced)
    corr_kernel<<<1024, 256>>>(0);    // fm -> g_fm + g_cm
    steps_kernel<<<NROW * CLUSTER, 1024, SMEM_STEPS>>>(aemb, proj, out);
}

// round 12
// speedup vs baseline: 1.8205x; 1.0419x over previous
#include <cuda_runtime.h>
#include <math.h>

#define TT    16384
#define AA    128
#define KK    128
#define NROW  4
#define NSTEP 16
#define EE    126
#define XSTR  260      // padded xc4 row stride in floats (multiple of 4)
#define CLUSTER 8      // CTAs per row; 16 atoms per CTA; 2048-col s_cm shard
#define NTHR  512

// ---------------- device scratch (static: no allocations allowed) ----------
__device__ __align__(16) float    g_du[AA * KK];
__device__ __align__(16) float    g_xc4[AA * 4 * AA * XSTR]; // ~68MB
__device__ __align__(16) float    g_fm[NROW * AA * TT];
__device__ __align__(16) float    g_res[NROW * TT];
__device__ __align__(16) unsigned g_cm[NROW * TT];           // encoded colmax
__device__ __align__(16) float    g_emb[NROW * NSTEP * 128];
__device__ float                  g_norm[NROW];
__device__ int                    g_done;

// order-preserving float->uint encoding (monotone bijection)
__device__ __forceinline__ unsigned fenc(float f) {
    unsigned u = __float_as_uint(f);
    return (u & 0x80000000u) ? ~u : (u | 0x80000000u);
}

__device__ __forceinline__ unsigned smem_u32(const void* p) {
    return (unsigned)__cvta_generic_to_shared(p);
}
__device__ __forceinline__ unsigned mapa_rank(unsigned addr, int r) {
    unsigned out;
    asm("mapa.shared::cluster.u32 %0, %1, %2;" : "=r"(out) : "r"(addr), "r"(r));
    return out;
}
__device__ __forceinline__ void st_remote_u32(unsigned addr, unsigned v) {
    asm volatile("st.shared::cluster.u32 [%0], %1;" :: "r"(addr), "r"(v) : "memory");
}
__device__ __forceinline__ void st_remote_u64(unsigned addr, unsigned long long v) {
    asm volatile("st.shared::cluster.u64 [%0], %1;" :: "r"(addr), "l"(v) : "memory");
}
#define CLUSTER_SYNC() do { \
    asm volatile("barrier.cluster.arrive.aligned;" ::: "memory"); \
    asm volatile("barrier.cluster.wait.aligned;"   ::: "memory"); \
} while (0)

// ---------------- prep: d_unit + residual/cm init + xc4 edge zero ----------
__global__ void prep_kernel(const float* __restrict__ a,
                            const float* __restrict__ b,
                            const float* __restrict__ d)
{
    __shared__ float sred[4];
    int bx = blockIdx.x;
    int tid = threadIdx.x; // 128
    if (bx == 0 && tid == 0) g_done = 0;
    if (bx < AA) {
        float v = d[bx * KK + tid];
        float ss = v * v;
        #pragma unroll
        for (int off = 16; off; off >>= 1)
            ss += __shfl_down_sync(0xffffffffu, ss, off);
        if ((tid & 31) == 0) sred[tid >> 5] = ss;
        __syncthreads();
        float tot = sred[0] + sred[1] + sred[2] + sred[3];
        g_du[bx * KK + tid] = v / (sqrtf(tot) + 1e-8f);
    } else if (bx < 384) {
        int base = (bx - AA) * 256;
        #pragma unroll
        for (int j = tid; j < 256; j += 128) {
            int i = base + j;
            g_res[i] = (i < 2 * TT) ? a[i] : b[i - 2 * TT];
            g_cm[i] = 0u;
        }
    } else {
        int bb = bx - 384;           // 0..511
        int ai = bb >> 2, s = bb & 3;
        int aa2 = tid;
        #pragma unroll
        for (int idx = 0; idx < 4; idx++) {
            int jp = (idx < s) ? idx : 256 + idx;
            g_xc4[((ai * 4 + s) * AA + aa2) * XSTR + jp] = 0.f;
        }
    }
}

// ---------------- correlation kernel, f32x2 (at fp32 FMA floor) ------------
__global__ __launch_bounds__(256) void corr_kernel(int mode)
{
    __shared__ float s_du[KK][64];   // 32KB; reused as 64x128 stage in mode 1
    __shared__ float s_sig[256];
    __shared__ float s_red[8][128];

    int blk = blockIdx.x;
    int tid = threadIdx.x;

    int row, tile, half;
    if (mode == 0) { half = blk & 1; row = (blk >> 1) & 3; tile = blk >> 3; }
    else           { half = blk & 1; tile = (blk >> 1) & 1; row = blk >> 2; }
    int t0 = tile * 128;

    for (int i = tid; i < 64 * KK; i += 256) {
        int al = i >> 7, k = i & 127;
        s_du[k][al] = g_du[(half * 64 + al) * KK + k];
    }

    const float* src;
    int srcLen, shift;
    if (mode == 0) { src = g_res + row * TT; srcLen = TT; shift = 64; }
    else           { src = g_du + row * KK;  srcLen = KK; shift = 127; }

    {
        int t = t0 + tid - shift;
        s_sig[tid] = (t >= 0 && t < srcLen) ? src[t] : 0.f;
    }
    __syncthreads();

    int x = tid & 31, y = tid >> 5;
    int c0 = x * 4, a0 = y * 8;

    unsigned long long acc2[4][4];
    #pragma unroll
    for (int j = 0; j < 4; j++)
        #pragma unroll
        for (int c = 0; c < 4; c++) acc2[j][c] = 0ull;

    unsigned r0 = __float_as_uint(s_sig[c0]);
    unsigned r1 = __float_as_uint(s_sig[c0 + 1]);
    unsigned r2 = __float_as_uint(s_sig[c0 + 2]);
    unsigned r3 = __float_as_uint(s_sig[c0 + 3]);

    #pragma unroll 4
    for (int k = 0; k < KK; k++) {
        unsigned long long dv[4];
        #pragma unroll
        for (int j = 0; j < 4; j++)
            dv[j] = *(const unsigned long long*)&s_du[k][a0 + 2 * j];

        unsigned long long rr0, rr1, rr2, rr3;
        asm("mov.b64 %0, {%1, %1};" : "=l"(rr0) : "r"(r0));
        asm("mov.b64 %0, {%1, %1};" : "=l"(rr1) : "r"(r1));
        asm("mov.b64 %0, {%1, %1};" : "=l"(rr2) : "r"(r2));
        asm("mov.b64 %0, {%1, %1};" : "=l"(rr3) : "r"(r3));

        #pragma unroll
        for (int j = 0; j < 4; j++) {
            asm("fma.rn.f32x2 %0, %1, %2, %0;" : "+l"(acc2[j][0]) : "l"(dv[j]), "l"(rr0));
            asm("fma.rn.f32x2 %0, %1, %2, %0;" : "+l"(acc2[j][1]) : "l"(dv[j]), "l"(rr1));
            asm("fma.rn.f32x2 %0, %1, %2, %0;" : "+l"(acc2[j][2]) : "l"(dv[j]), "l"(rr2));
            asm("fma.rn.f32x2 %0, %1, %2, %0;" : "+l"(acc2[j][3]) : "l"(dv[j]), "l"(rr3));
        }
        r0 = r1; r1 = r2; r2 = r3;
        r3 = __float_as_uint(s_sig[c0 + 4 + k]);
    }

    int a_base = half * 64 + a0;
    int t = t0 + c0;

    if (mode == 0) {
        float* out = g_fm + row * AA * TT;
        float cmax[4] = { -3.402823466e38f, -3.402823466e38f,
                          -3.402823466e38f, -3.402823466e38f };
        #pragma unroll
        for (int j = 0; j < 4; j++) {
            float lo[4], hi[4];
            #pragma unroll
            for (int c = 0; c < 4; c++) {
                lo[c] = __uint_as_float((unsigned)acc2[j][c]);
                hi[c] = __uint_as_float((unsigned)(acc2[j][c] >> 32));
                cmax[c] = fmaxf(cmax[c], fmaxf(lo[c], hi[c]));
            }
            *(float4*)(out + (a_base + 2 * j) * TT + t) =
                make_float4(lo[0], lo[1], lo[2], lo[3]);
            *(float4*)(out + (a_base + 2 * j + 1) * TT + t) =
                make_float4(hi[0], hi[1], hi[2], hi[3]);
        }
        #pragma unroll
        for (int c = 0; c < 4; c++) s_red[y][c0 + c] = cmax[c];
        __syncthreads();
        if (tid < 128) {
            float m = s_red[0][tid];
            #pragma unroll
            for (int w = 1; w < 8; w++) m = fmaxf(m, s_red[w][tid]);
            atomicMax(&g_cm[row * TT + t0 + tid], fenc(m));
        }
    } else {
        // stage 64x128 tile, then coalesced shifted copies
        float* s_stage = &s_du[0][0];
        __syncthreads();
        #pragma unroll
        for (int j = 0; j < 4; j++) {
            float lo[4], hi[4];
            #pragma unroll
            for (int c = 0; c < 4; c++) {
                lo[c] = __uint_as_float((unsigned)acc2[j][c]);
                hi[c] = __uint_as_float((unsigned)(acc2[j][c] >> 32));
            }
            *(float4*)(s_stage + (a0 + 2 * j) * 128 + c0) =
                make_float4(lo[0], lo[1], lo[2], lo[3]);
            *(float4*)(s_stage + (a0 + 2 * j + 1) * 128 + c0) =
                make_float4(hi[0], hi[1], hi[2], hi[3]);
        }
        __syncthreads();

        #pragma unroll
        for (int s = 0; s < 4; s++) {
            int nF4 = (s == 0) ? 32 : 31;
            for (int i = tid; i < 64 * nF4; i += 256) {
                int a = i / nF4, mi = i - a * nF4;
                int localc = (s == 0) ? (4 * mi) : (4 + 4 * mi - s);
                int dstf4  = (s == 0) ? (t0 / 4 + mi) : (t0 / 4 + 1 + mi);
                const float* sp = s_stage + a * 128 + localc;
                float4 v = make_float4(sp[0], sp[1], sp[2], sp[3]);
                long base = ((long)(row * 4 + s) * AA + half * 64 + a) * XSTR;
                *(float4*)(g_xc4 + base + 4 * dstf4) = v;
            }
            if (s > 0) {
                for (int i = tid; i < 64 * 4; i += 256) {
                    int a = i >> 2, q = i & 3;
                    long base = ((long)(row * 4 + s) * AA + half * 64 + a) * XSTR;
                    if (q < 4 - s) {
                        g_xc4[base + t0 + s + q] = s_stage[a * 128 + q];
                    } else {
                        int qq = q - (4 - s);
                        g_xc4[base + t0 + 128 + qq] = s_stage[a * 128 + 128 - s + qq];
                    }
                }
            }
        }
    }
}

// ---------------- steps: cluster of 8 CTAs per row, SHARDED colmax ---------
// dynamic smem per CTA:
//   s_cm   [2048 u32]   8192 B  (owned 2048-col shard: cols [rank*2048, +2048))
//   s_tile [16*XSTR f] 16640 B  (local window tile for this rank's 16 atoms)
//   s_part [8][260]u32  8320 B  (window partials received from each src rank)
//   s_w    [260 u32]    1040 B  (local window partial)
//   s_best [8 u64]        64 B  (per-rank best candidates)
#define OFF_TILE   8192
#define OFF_PART   (OFF_TILE + 16 * XSTR * 4)
#define OFF_W      (OFF_PART + 8 * 260 * 4)
#define OFF_BEST   (OFF_W + 260 * 4)
#define SMEM_STEPS (OFF_BEST + 8 * 8 + 16)

__global__ __launch_bounds__(NTHR, 1) __cluster_dims__(CLUSTER, 1, 1)
void steps_kernel(const float* __restrict__ atom_emb,
                  const float* __restrict__ proj,
                  float* __restrict__ out)
{
    extern __shared__ unsigned char smem_raw[];
    unsigned*           s_cm   = (unsigned*)smem_raw;
    float*              s_tile = (float*)(smem_raw + OFF_TILE);
    unsigned*           s_part = (unsigned*)(smem_raw + OFF_PART);  // [src][260]
    unsigned*           s_w    = (unsigned*)(smem_raw + OFF_W);
    unsigned long long* s_best = (unsigned long long*)(smem_raw + OFF_BEST);

    __shared__ unsigned long long s_lb[16];
    __shared__ float s_nred[16];
    __shared__ float sh_v;
    __shared__ int   sh_ti, sh_ai, sh_pa, sh_aa;
    __shared__ int   s_last;
    __shared__ float s_keys[64];
    __shared__ int   s_order[64];
    __shared__ float s_proj[128];

    int r    = blockIdx.x / CLUSTER;
    int rank = blockIdx.x % CLUSTER;
    int tid  = threadIdx.x;
    int lane = tid & 31, wid = tid >> 5;
    int my_base = rank * 2048;

    float* fmr  = g_fm  + r * AA * TT;
    float* resr = g_res + r * TT;

    // load owned colmax shard
    ((uint4*)s_cm)[tid] = ((const uint4*)(g_cm + r * TT + my_base))[tid];
    __syncthreads();

    int prev_w0 = 0;

    for (int step = 0; step < NSTEP; step++) {
        // --- A: owners fold prev-step window partials into owned shard ---
        if (step > 0 && tid < 260) {
            int t = prev_w0 + tid;
            if (t >= 0 && t < TT && (t >> 11) == rank) {
                unsigned m = s_part[tid];
                #pragma unroll
                for (int src = 1; src < 8; src++) {
                    unsigned mm = s_part[src * 260 + tid];
                    if (mm > m) m = mm;
                }
                s_cm[t - my_base] = m;
            }
        }
        __syncthreads();

        // --- B: local argmax over owned 2048 cols; key = (enc<<32)|(~t) ---
        {
            uint4 u = ((const uint4*)s_cm)[tid];
            int tb = my_base + tid * 4;
            unsigned long long k =
                ((unsigned long long)u.x << 32) | (unsigned)(0xFFFFFFFFu - tb);
            unsigned long long k1 =
                ((unsigned long long)u.y << 32) | (unsigned)(0xFFFFFFFFu - (tb + 1));
            unsigned long long k2 =
                ((unsigned long long)u.z << 32) | (unsigned)(0xFFFFFFFFu - (tb + 2));
            unsigned long long k3 =
                ((unsigned long long)u.w << 32) | (unsigned)(0xFFFFFFFFu - (tb + 3));
            if (k1 > k) k = k1;
            if (k2 > k) k = k2;
            if (k3 > k) k = k3;
            #pragma unroll
            for (int off = 16; off; off >>= 1) {
                unsigned long long o = __shfl_down_sync(0xffffffffu, k, off);
                if (o > k) k = o;
            }
            if (lane == 0) s_lb[wid] = k;
        }
        __syncthreads();
        if (wid == 0) {
            unsigned long long k = (lane < 16) ? s_lb[lane] : 0ull;
            #pragma unroll
            for (int off = 8; off; off >>= 1) {
                unsigned long long o = __shfl_down_sync(0xffffffffu, k, off);
                if (o > k) k = o;
            }
            if (lane == 0) {
                unsigned loc = smem_u32(&s_best[rank]);
                s_best[rank] = k;
                #pragma unroll
                for (int d = 0; d < 8; d++)
                    if (d != rank) st_remote_u64(mapa_rank(loc, d), k);
            }
        }
        CLUSTER_SYNC();   // S1: all 8 candidates visible everywhere

        // --- C: global reduce (8 candidates) + atom argmax (warp 0) ---
        if (wid == 0) {
            unsigned long long k = s_best[lane & 7];
            #pragma unroll
            for (int off = 1; off < 8; off <<= 1) {
                unsigned long long o = __shfl_xor_sync(0xffffffffu, k, off);
                if (o > k) k = o;
            }
            int bt = (int)(0xFFFFFFFFu - (unsigned)(k & 0xFFFFFFFFull));

            float av = -3.402823466e38f;
            int aarg = 0x7fffffff;
            #pragma unroll
            for (int a4 = 0; a4 < 4; a4++) {
                int a = lane + 32 * a4;
                float fv = __ldcg(&fmr[a * TT + bt]);
                if (fv > av) { av = fv; aarg = a; }
            }
            #pragma unroll
            for (int off = 16; off; off >>= 1) {
                float ov = __shfl_down_sync(0xffffffffu, av, off);
                int   oa = __shfl_down_sync(0xffffffffu, aarg, off);
                if (ov > av || (ov == av && oa < aarg)) { av = ov; aarg = oa; }
            }
            if (lane == 0) {
                sh_v = av; sh_ti = bt; sh_ai = aarg;
                int pa, aa2;
                if (av > 0.f)      { pa = bt; aa2 = aarg; }
                else if (av < 0.f) { pa = (bt == 0) ? 1 : 0; aa2 = (aarg == 0) ? 1 : 0; }
                else               { pa = 0; aa2 = 0; }
                sh_pa = pa; sh_aa = aa2;
            }
        }
        __syncthreads();

        float v = sh_v;
        int ti = sh_ti, ai = sh_ai;
        int w0  = (ti - 127) & ~3;
        int shf = (ti - 127) - w0;

        // --- D: rank 0 emb + residual; zero s_w (threads 252..511) ---
        if (rank == 0 && tid < 128) {
            float e;
            if (tid == 0)      e = (float)sh_pa * (20.f / (float)(TT - 1));
            else if (tid == 1) e = v;
            else               e = atom_emb[sh_aa * EE + (tid - 2)];
            g_emb[(r * NSTEP + step) * 128 + tid] = e;
        } else if (rank == 0 && tid < 256) {
            int k = tid - 128;
            int t = ti - 64 + k;
            if (t >= 0 && t < TT) resr[t] -= v * g_du[ai * KK + k];
        }
        if (tid >= 252) s_w[tid - 252] = 0u;

        // --- E: phase 3b fm window update; warp wid owns atom rank*16+wid ---
        {
            int a = rank * 16 + wid;
            float*       fp = fmr + a * TT;
            const float* xp = g_xc4 + ((long)(ai * 4 + shf) * AA + a) * XSTR;
            float*       tp = s_tile + wid * XSTR;
            #pragma unroll
            for (int it = 0; it < 3; it++) {
                int jj4 = lane + 32 * it;
                if (jj4 < 65) {
                    int jp = jj4 * 4;
                    int t = w0 + jp;
                    if (t >= 0 && t + 3 < TT) {
                        float4 f = *(const float4*)(fp + t);
                        float4 xx = *(const float4*)(xp + jp);
                        f.x -= v * xx.x; f.y -= v * xx.y;
                        f.z -= v * xx.z; f.w -= v * xx.w;
                        *(float4*)(fp + t) = f;
                        *(float4*)(tp + jp) = f;
                    } else {
                        #pragma unroll
                        for (int e = 0; e < 4; e++) {
                            int te = t + e;
                            if (te >= 0 && te < TT) {
                                float f = fp[te] - v * xp[jp + e];
                                fp[te] = f;
                                tp[jp + e] = f;
                            }
                        }
                    }
                }
            }
        }
        __syncthreads();

        // --- F: local colmax partial over 16 atoms -> s_w ---
        {
            int c4 = tid & 63, sub = tid >> 6;    // 8 subs x 2 atoms
            #pragma unroll
            for (int pass = 0; pass < 2; pass++) {
                int cc4, ss;
                if (pass == 0) { cc4 = c4; ss = sub; }
                else { if (tid >= 8) break; cc4 = 64; ss = tid; }
                float m0 = -3.402823466e38f, m1 = m0, m2 = m0, m3 = m0;
                #pragma unroll
                for (int i = 0; i < 2; i++) {
                    int a = ss * 2 + i;
                    float4 xx = *(const float4*)(s_tile + a * XSTR + 4 * cc4);
                    m0 = fmaxf(m0, xx.x); m1 = fmaxf(m1, xx.y);
                    m2 = fmaxf(m2, xx.z); m3 = fmaxf(m3, xx.w);
                }
                int cb = 4 * cc4;
                atomicMax(&s_w[cb],     fenc(m0));
                atomicMax(&s_w[cb + 1], fenc(m1));
                atomicMax(&s_w[cb + 2], fenc(m2));
                atomicMax(&s_w[cb + 3], fenc(m3));
            }
        }
        __syncthreads();

        // --- G: export partials to the OWNER rank of each window col ---
        if (tid < 260) {
            int t = w0 + tid;
            if (t >= 0 && t < TT) {
                int owner = t >> 11;
                unsigned val = s_w[tid];
                unsigned loc = smem_u32(&s_part[rank * 260 + tid]);
                if (owner == rank) s_part[rank * 260 + tid] = val;
                else st_remote_u32(mapa_rank(loc, owner), val);
            }
        }
        prev_w0 = w0;
        CLUSTER_SYNC();   // S2: partials + fm gmem writes visible
    }

    if (rank != 0) return;   // last cluster op was S2; safe to diverge

    // --- residual norm (rank 0) ---
    float ss = 0.f;
    #pragma unroll
    for (int q = 0; q < 8; q++) {
        float4 vv = ((const float4*)resr)[tid + NTHR * q];
        ss += vv.x * vv.x + vv.y * vv.y + vv.z * vv.z + vv.w * vv.w;
    }
    #pragma unroll
    for (int off = 16; off; off >>= 1)
        ss += __shfl_down_sync(0xffffffffu, ss, off);
    if (lane == 0) s_nred[wid] = ss;
    __syncthreads();
    if (wid == 0) {
        float t2 = (lane < 16) ? s_nred[lane] : 0.f;
        #pragma unroll
        for (int off = 8; off; off >>= 1)
            t2 += __shfl_down_sync(0xffffffffu, t2, off);
        if (lane == 0) g_norm[r] = sqrtf(t2);
    }

    // --- fused final loss: last rank-0 to finish computes it ---
    __threadfence();
    __syncthreads();
    if (tid == 0) s_last = (atomicAdd(&g_done, 1) == NROW - 1);
    __syncthreads();
    if (!s_last) return;
    __threadfence();

    if (tid < 128) s_proj[tid] = proj[tid];
    __syncthreads();

    // keys: 16 warps x 4 keys (8 lanes per key)
    {
        int key = wid * 4 + (lane >> 3);
        int sl = lane & 7;
        const float* e = g_emb + key * 128;
        float p = 0.f;
        #pragma unroll
        for (int q = 0; q < 16; q++) {
            int j = sl + 8 * q;
            p += e[j] * s_proj[j];
        }
        #pragma unroll
        for (int off = 1; off < 8; off <<= 1)
            p += __shfl_xor_sync(0xffffffffu, p, off);
        if (sl == 0) s_keys[key] = p;
    }
    __syncthreads();

    if (tid < 4) {   // stable insertion sort, ascending (matches jnp.argsort)
        int ord[16];
        for (int i = 0; i < 16; i++) ord[i] = i;
        for (int i = 1; i < 16; i++) {
            int oi = ord[i];
            float ki = s_keys[tid * 16 + oi];
            int j = i - 1;
            while (j >= 0 && s_keys[tid * 16 + ord[j]] > ki) { ord[j + 1] = ord[j]; j--; }
            ord[j + 1] = oi;
        }
        for (int i = 0; i < 16; i++) s_order[tid * 16 + i] = ord[i];
    }
    __syncthreads();

    float acc = 0.f;
    #pragma unroll
    for (int q = 0; q < 8; q++) {
        int i = tid + NTHR * q;
        int bb = i >> 11;
        int st = (i >> 7) & 15;
        int e = i & 127;
        int sa = s_order[bb * 16 + st];
        int sb = s_order[(2 + bb) * 16 + st];
        float dd = g_emb[(bb * 16 + sa) * 128 + e] - g_emb[((2 + bb) * 16 + sb) * 128 + e];
        acc += dd * dd;
    }
    #pragma unroll
    for (int off = 16; off; off >>= 1)
        acc += __shfl_down_sync(0xffffffffu, acc, off);
    if (lane == 0) s_nred[wid] = acc;
    __syncthreads();
    if (tid == 0) {
        float t2 = 0.f;
        for (int w = 0; w < 16; w++) t2 += s_nred[w];
        out[0] = t2 / 4096.f
               + 0.5f * (fabsf(g_norm[0] - g_norm[2]) + fabsf(g_norm[1] - g_norm[3]));
    }
}

// ---------------- launch ----------------------------------------------------
extern "C" void kernel_launch(void* const* d_in, const int* in_sizes, int n_in,
                              void* d_out, int out_size)
{
    (void)in_sizes; (void)n_in; (void)out_size;
    const float* a    = (const float*)d_in[0];
    const float* b    = (const float*)d_in[1];
    const float* d    = (const float*)d_in[2];
    const float* aemb = (const float*)d_in[3];
    const float* proj = (const float*)d_in[4];
    float* out = (float*)d_out;

    cudaFuncSetAttribute(steps_kernel,
                         cudaFuncAttributeMaxDynamicSharedMemorySize, SMEM_STEPS);

    prep_kernel<<<896, 128>>>(a, b, d);
    corr_kernel<<<512, 256>>>(1);     // xcorr -> g_xc4 (staged, coalesced)
    corr_kernel<<<1024, 256>>>(0);    // fm -> g_fm + g_cm
    steps_kernel<<<NROW * CLUSTER, NTHR, SMEM_STEPS>>>(aemb, proj, out);
}